// round 11
// baseline (speedup 1.0000x reference)
#include <cuda_runtime.h>
#include <cuda_bf16.h>
#include <cstdint>

// VQ-VAE forward on GB300 (base sm_103 target: mma.sync/ldmatrix/cp.async).
// Outputs (flattened, in order): recon (32,3,128,128), z_e (32,512,32,32), emb (32,512,32,32)

#define NB 32
#define NC 3
#define NH 128
#define ND 512
#define NK 512
#define NHL 32
#define NL 1024
#define NM (NB * NL)  // 32768

#define RECON_N (32 * 3 * 128 * 128)
#define ZE_N (32 * 512 * 32 * 32)
#define MARGIN 0.45f
#define NSLOT 16

// ---------------- scratch (static device memory; no allocations) ----------------
__device__ __nv_bfloat16 g_zh[NM * ND];   // z_e hi split, row-major (M, D)
__device__ __nv_bfloat16 g_zl[NM * ND];   // z_e lo split
__device__ __nv_bfloat16 g_cbh[NK * ND];  // codebook^T bf16 (K, D)
__device__ float g_cbt[NK * ND];          // codebook^T fp32 (K, D)
__device__ float g_w2[NK];                // ||W[:,k]||^2 (fp32 exact)
__device__ float g_wdt[48 * ND];          // decoder weights, spatial flip baked in
__device__ int   g_idx[NM];               // final argmin indices
__device__ unsigned long long g_key[NM];  // pass-1 packed (approx dist, k)
__device__ int g_ccnt[NM];                // candidate counts
__device__ unsigned long long g_cand[NM * NSLOT];  // candidate packed (dist, k)

// ---------------- small helpers ----------------
__device__ __forceinline__ unsigned mapf(float x) {
    unsigned u = __float_as_uint(x);
    return (u & 0x80000000u) ? ~u : (u | 0x80000000u);   // order-preserving
}
__device__ __forceinline__ float unmapf(unsigned m) {
    unsigned u = (m & 0x80000000u) ? (m ^ 0x80000000u) : ~m;
    return __uint_as_float(u);
}

#define CP_ASYNC16(smaddr, gptr) \
    asm volatile("cp.async.cg.shared.global [%0], [%1], 16;" :: "r"(smaddr), "l"(gptr))
#define CP_COMMIT() asm volatile("cp.async.commit_group;" ::: "memory")
#define CP_WAIT(n)  asm volatile("cp.async.wait_group %0;" :: "n"(n) : "memory")

__device__ __forceinline__ void ldsm4(uint32_t& r0, uint32_t& r1, uint32_t& r2, uint32_t& r3,
                                      uint32_t addr) {
    asm volatile("ldmatrix.sync.aligned.m8n8.x4.shared.b16 {%0,%1,%2,%3}, [%4];"
                 : "=r"(r0), "=r"(r1), "=r"(r2), "=r"(r3) : "r"(addr));
}
__device__ __forceinline__ void mma16816(float* c, const uint32_t* a, uint32_t b0, uint32_t b1) {
    asm volatile(
        "mma.sync.aligned.m16n8k16.row.col.f32.bf16.bf16.f32 "
        "{%0,%1,%2,%3}, {%4,%5,%6,%7}, {%8,%9}, {%0,%1,%2,%3};"
        : "+f"(c[0]), "+f"(c[1]), "+f"(c[2]), "+f"(c[3])
        : "r"(a[0]), "r"(a[1]), "r"(a[2]), "r"(a[3]), "r"(b0), "r"(b1));
}

// ---------------- prep 1: codebook transpose (D,K)->(K,D) + bf16 split ----------------
__global__ void k_prep_cbt(const float* __restrict__ cb) {
    __shared__ float t[32][33];
    int x = blockIdx.x * 32 + threadIdx.x;
    int y0 = blockIdx.y * 32;
    for (int r = threadIdx.y; r < 32; r += 8)
        t[r][threadIdx.x] = cb[(y0 + r) * NK + x];
    __syncthreads();
    int xo = blockIdx.y * 32 + threadIdx.x;
    int yo = blockIdx.x * 32;
    for (int r = threadIdx.y; r < 32; r += 8) {
        float v = t[threadIdx.x][r];
        g_cbt[(yo + r) * ND + xo] = v;
        g_cbh[(yo + r) * ND + xo] = __float2bfloat16(v);
    }
}

// ---------------- prep 2 (fused): wdt / w2 / key-init, range-partitioned ----------------
__global__ void k_prep2(const float* __restrict__ Wd) {
    int blk = blockIdx.x, tid = threadIdx.x;
    if (blk < 96) {
        int e = blk * 256 + tid;   // 48*512 = 24576
        int r = e >> 9, d = e & 511;
        int c = r >> 4, i = (r >> 2) & 3, j = r & 3;
        g_wdt[e] = Wd[(c * ND + d) * 16 + (3 - i) * 4 + (3 - j)];
    } else if (blk < 98) {
        int k = (blk - 96) * 256 + tid;
        const float* row = g_cbt + k * ND;
        float s = 0.f;
        for (int d = 0; d < ND; d += 4) {
            float4 v = *reinterpret_cast<const float4*>(row + d);
            s += v.x * v.x + v.y * v.y + v.z * v.z + v.w * v.w;
        }
        g_w2[k] = s;
    } else {
        int m = (blk - 98) * 256 + tid;   // 128 blocks -> 32768
        g_key[m] = 0xFFFFFFFFFFFFFFFFull;
        g_ccnt[m] = 0;
    }
}

// ---------------- encode: patch-embed GEMM + bias + relu ----------------
// grid (1024, 4): x = (b,hl); y: bit0 = position half (16 wl), bit1 = d half (256).
__global__ __launch_bounds__(256) void k_encode(const float* __restrict__ x,
                                                const float* __restrict__ We,
                                                const float* __restrict__ be,
                                                float* __restrict__ out_ze) {
    extern __shared__ float esm[];
    float* patch = esm;           // [16][48]
    float* wsm = esm + 16 * 48;   // [256][48]
    int blk = blockIdx.x;
    int b = blk >> 5, hl = blk & 31;
    int ph = blockIdx.y & 1, dh = blockIdx.y >> 1;
    int tid = threadIdx.x;

    for (int e = tid; e < 256 * 48; e += 256)
        wsm[e] = We[dh * (256 * 48) + e];
    for (int e = tid; e < 768; e += 256) {
        int row = e >> 6, cc = e & 63;
        int c = row >> 2, i = row & 3;
        float v = x[((b * NC + c) * NH + (4 * hl + i)) * NH + ph * 64 + cc];
        patch[(cc >> 2) * 48 + c * 16 + i * 4 + (cc & 3)] = v;
    }
    __syncthreads();

    int d = dh * 256 + tid;
    float w[48];
#pragma unroll
    for (int q = 0; q < 48; q++) w[q] = wsm[tid * 48 + q];
    float bias = be[d];

    float acc[16];
    int mbase = b * NL + hl * 32 + ph * 16;
#pragma unroll
    for (int pos = 0; pos < 16; pos++) {
        float p0 = bias, p1 = 0.f, p2 = 0.f, p3 = 0.f;
        const float* pp = patch + pos * 48;
#pragma unroll
        for (int q = 0; q < 12; q++) {
            float* dst = (q & 3) == 0 ? &p0 : (q & 3) == 1 ? &p1 : (q & 3) == 2 ? &p2 : &p3;
            *dst += pp[4*q] * w[4*q] + pp[4*q+1] * w[4*q+1] + pp[4*q+2] * w[4*q+2] + pp[4*q+3] * w[4*q+3];
        }
        float v = fmaxf((p0 + p1) + (p2 + p3), 0.f);
        acc[pos] = v;
        __nv_bfloat16 h = __float2bfloat16(v);
        int zi = (mbase + pos) * ND + d;
        g_zh[zi] = h;
        g_zl[zi] = __float2bfloat16(v - __bfloat162float(h));
    }
    float4* o4 = reinterpret_cast<float4*>(out_ze + ((b * ND + d) * NHL + hl) * NHL + ph * 16);
#pragma unroll
    for (int q = 0; q < 4; q++)
        o4[q] = make_float4(acc[4*q], acc[4*q+1], acc[4*q+2], acc[4*q+3]);
}

// ---------------- pass 1: bf16 HMMA GEMM + approx argmin + candidate flagging ----------------
// Block tile 128(m) x 256(n); warp grid 2(m) x 4(n), warp tile 64x64.
// 3-stage cp.async pipeline: stage = A[128][144B] + B[256][144B] = 55296 B.
#define STG 55296
#define NN_SMEM (3 * STG)   // 165888 B; 1 block/SM

__global__ __launch_bounds__(256, 1) void k_nn() {
    extern __shared__ __align__(16) char nsm[];
    __shared__ float w2s[256];
    __shared__ unsigned rmin[128];
    int tid = threadIdx.x;
    int lane = tid & 31, wrp = tid >> 5;
    int wm = wrp & 1, wn = wrp >> 1;      // 2 x 4 warp grid; warp tile 64(m) x 64(n)
    int m0 = blockIdx.x * 128, n0 = blockIdx.y * 256;
    uint32_t smb = (uint32_t)__cvta_generic_to_shared(nsm);

    // fill bases (folded: per cp.async only immediate-style adds remain)
    int tr = tid >> 3, cg = tid & 7;
    uint32_t so0 = (uint32_t)(tr * 144 + cg * 16);
    const __nv_bfloat16* pa0 = g_zh + (m0 + tr) * ND + cg * 8;
    const __nv_bfloat16* pb0 = g_cbh + (n0 + tr) * ND + cg * 8;

    auto fill = [&](int stage, int kc) {
        uint32_t ab = smb + stage * STG + so0;
        uint32_t bb = ab + 18432;
        const __nv_bfloat16* ap = pa0 + kc * 64;
        const __nv_bfloat16* bp = pb0 + kc * 64;
#pragma unroll
        for (int i = 0; i < 4; i++) CP_ASYNC16(ab + i * 4608, ap + i * (32 * ND));
#pragma unroll
        for (int i = 0; i < 8; i++) CP_ASYNC16(bb + i * 4608, bp + i * (32 * ND));
    };

    w2s[tid] = g_w2[n0 + tid];
    if (tid < 128) rmin[tid] = 0xFFFFFFFFu;

    float cfr[4][8][4];
#pragma unroll
    for (int mt = 0; mt < 4; mt++)
#pragma unroll
        for (int nt = 0; nt < 8; nt++)
#pragma unroll
            for (int q = 0; q < 4; q++) cfr[mt][nt][q] = 0.f;

    fill(0, 0); CP_COMMIT();
    fill(1, 1); CP_COMMIT();

    for (int kc = 0; kc < 8; kc++) {
        if (kc < 6) { CP_WAIT(1); } else { CP_WAIT(0); }
        __syncthreads();   // stage kc ready; all warps done with stage (kc-1)
        if (kc < 6) { fill((kc + 2) % 3, kc + 2); CP_COMMIT(); }
        uint32_t sa = smb + (kc % 3) * STG;
        uint32_t sb = sa + 18432;
#pragma unroll
        for (int ks = 0; ks < 4; ks++) {
            uint32_t afr[4][4];
#pragma unroll
            for (int mt = 0; mt < 4; mt++) {
                int r = wm * 64 + mt * 16 + ((lane >> 3) & 1) * 8 + (lane & 7);
                int cb = ks * 32 + (lane >> 4) * 16;
                ldsm4(afr[mt][0], afr[mt][1], afr[mt][2], afr[mt][3], sa + r * 144 + cb);
            }
            uint32_t bfr[8][2];
#pragma unroll
            for (int p = 0; p < 4; p++) {
                int r = wn * 64 + p * 16 + (lane >> 4) * 8 + (lane & 7);
                int cb = ks * 32 + ((lane >> 3) & 1) * 16;
                uint32_t b0, b1, b2, b3;
                ldsm4(b0, b1, b2, b3, sb + r * 144 + cb);
                bfr[2*p][0] = b0; bfr[2*p][1] = b1; bfr[2*p+1][0] = b2; bfr[2*p+1][1] = b3;
            }
#pragma unroll
            for (int mt = 0; mt < 4; mt++)
#pragma unroll
                for (int nt = 0; nt < 8; nt++)
                    mma16816(cfr[mt][nt], afr[mt], bfr[nt][0], bfr[nt][1]);
        }
    }

    // epilogue phase 1: per-row block min (smem) + global packed atomicMin
#pragma unroll
    for (int mt = 0; mt < 4; mt++) {
#pragma unroll
        for (int h = 0; h < 2; h++) {
            int lr = wm * 64 + mt * 16 + (lane >> 2) + h * 8;
            unsigned long long best = 0xFFFFFFFFFFFFFFFFull;
#pragma unroll
            for (int nt = 0; nt < 8; nt++)
#pragma unroll
                for (int c2 = 0; c2 < 2; c2++) {
                    int kl = wn * 64 + nt * 8 + (lane & 3) * 2 + c2;
                    float dist = w2s[kl] - 2.f * cfr[mt][nt][h * 2 + c2];
                    unsigned long long key =
                        ((unsigned long long)mapf(dist) << 32) | (unsigned)(n0 + kl);
                    if (key < best) best = key;
                }
            unsigned long long o1 = __shfl_xor_sync(0xffffffffu, best, 1);
            if (o1 < best) best = o1;
            unsigned long long o2 = __shfl_xor_sync(0xffffffffu, best, 2);
            if (o2 < best) best = o2;
            if ((lane & 3) == 0) {
                atomicMin(&rmin[lr], (unsigned)(best >> 32));
                atomicMin(&g_key[m0 + lr], best);
            }
        }
    }
    __syncthreads();

    // epilogue phase 2: flag candidates (store packed key) within MARGIN of block row-min
#pragma unroll
    for (int mt = 0; mt < 4; mt++) {
#pragma unroll
        for (int h = 0; h < 2; h++) {
            int lr = wm * 64 + mt * 16 + (lane >> 2) + h * 8;
            float thr = unmapf(rmin[lr]) + MARGIN;
#pragma unroll
            for (int nt = 0; nt < 8; nt++)
#pragma unroll
                for (int c2 = 0; c2 < 2; c2++) {
                    int kl = wn * 64 + nt * 8 + (lane & 3) * 2 + c2;
                    float dist = w2s[kl] - 2.f * cfr[mt][nt][h * 2 + c2];
                    if (dist <= thr) {
                        int pos = atomicAdd(&g_ccnt[m0 + lr], 1);
                        if (pos < NSLOT)
                            g_cand[(m0 + lr) * NSLOT + pos] =
                                ((unsigned long long)mapf(dist) << 32) | (unsigned)(n0 + kl);
                    }
                }
        }
    }
}

// ---------------- pass 2: exact fp32 rescore (fast path: approx winner unambiguous) ----------------
__global__ __launch_bounds__(256) void k_rescore() {
    int tid = threadIdx.x, lane = tid & 31;
    int m = blockIdx.x * 8 + (tid >> 5);

    unsigned long long gkey = g_key[m];
    float amin = unmapf((unsigned)(gkey >> 32));
    int kstar = (int)(gkey & 0xFFFFFFFFu);
    int cnt = g_ccnt[m]; if (cnt > NSLOT) cnt = NSLOT;

    unsigned long long ck = 0xFFFFFFFFFFFFFFFFull;
    if (lane < cnt) ck = g_cand[m * NSLOT + lane];
    bool qual = (lane < cnt) && (ck != gkey) &&
                (unmapf((unsigned)(ck >> 32)) <= amin + MARGIN);
    unsigned bal = __ballot_sync(0xffffffffu, qual);
    if (bal == 0) {   // no challenger within global margin: approx winner is exact
        if (lane == 0) g_idx[m] = kstar;
        return;
    }

    // slow path: reconstruct z (fp32 from hi+lo) and exactly rescore kstar + challengers
    float4 z[4];
#pragma unroll
    for (int t = 0; t < 4; t++) {
        int d = t * 128 + lane * 4;
        uint2 hh = *reinterpret_cast<const uint2*>(g_zh + m * ND + d);
        uint2 ll = *reinterpret_cast<const uint2*>(g_zl + m * ND + d);
        __nv_bfloat162 h0 = *reinterpret_cast<__nv_bfloat162*>(&hh.x);
        __nv_bfloat162 h1 = *reinterpret_cast<__nv_bfloat162*>(&hh.y);
        __nv_bfloat162 l0 = *reinterpret_cast<__nv_bfloat162*>(&ll.x);
        __nv_bfloat162 l1 = *reinterpret_cast<__nv_bfloat162*>(&ll.y);
        z[t].x = __bfloat162float(h0.x) + __bfloat162float(l0.x);
        z[t].y = __bfloat162float(h0.y) + __bfloat162float(l0.y);
        z[t].z = __bfloat162float(h1.x) + __bfloat162float(l1.x);
        z[t].w = __bfloat162float(h1.y) + __bfloat162float(l1.y);
    }
    unsigned mycand = (unsigned)(ck & 0xFFFFFFFFu);
    unsigned long long best = 0xFFFFFFFFFFFFFFFFull;
    int k = kstar;
    unsigned rem = bal;
    for (;;) {
        float s = 0.f;
#pragma unroll
        for (int t = 0; t < 4; t++) {
            float4 cv = *reinterpret_cast<const float4*>(g_cbt + k * ND + t * 128 + lane * 4);
            s += z[t].x * cv.x + z[t].y * cv.y + z[t].z * cv.z + z[t].w * cv.w;
        }
#pragma unroll
        for (int off = 16; off > 0; off >>= 1) s += __shfl_xor_sync(0xffffffffu, s, off);
        float dist = g_w2[k] - 2.f * s;
        unsigned long long key = ((unsigned long long)mapf(dist) << 32) | (unsigned)k;
        if (key < best) best = key;
        if (!rem) break;
        int src = __ffs(rem) - 1;
        rem &= rem - 1;
        k = (int)__shfl_sync(0xffffffffu, mycand, src);
    }
    if (lane == 0) g_idx[m] = (int)(best & 0xFFFFFFFFu);
}

// ---------------- gather (emb) + decode (recon) ----------------
// zq pitch 517 (conflict-free broadcast), wds pitch 524 (conflict-free row groups).
#define ZQP 517
#define WDP 524
#define GDE_SMEM ((32 * ZQP + 48 * WDP + 1536) * 4)
__global__ __launch_bounds__(512) void k_gde(const float* __restrict__ bd,
                                             float* __restrict__ out_emb,
                                             float* __restrict__ out_recon) {
    extern __shared__ float smf[];
    float* zq = smf;                       // [32][ZQP]
    float* wds = smf + 32 * ZQP;           // [48][WDP]
    float* part = smf + 32 * ZQP + 48 * WDP;  // [32*48]
    __shared__ int karr[32];

    int blk = blockIdx.x;
    int b = blk >> 5, hl = blk & 31;
    int tid = threadIdx.x;

    if (tid < 32) karr[tid] = g_idx[b * NL + hl * 32 + tid];
    for (int e = tid; e < 48 * ND; e += 512) {
        int r = e >> 9, d = e & 511;
        wds[r * WDP + d] = g_wdt[e];
    }
    __syncthreads();
    for (int e = tid; e < 32 * ND; e += 512) {
        int wl = e >> 9, d = e & 511;
        zq[wl * ZQP + d] = g_cbt[karr[wl] * ND + d];
    }
    __syncthreads();

    // emb output (B,D,L)
    float* eb = out_emb + b * (ND * NL) + hl * 32;
    for (int e = tid; e < 16384; e += 512) {
        int d = e >> 5, wl = e & 31;
        eb[d * NL + wl] = zq[wl * ZQP + d];
    }

    // decode: register-tiled 4(wl) x 6(r) per thread, d interleaved stride 8.
    {
        int lane = tid & 31, w = tid >> 5;
        int dq = lane & 7;
        int rg = ((lane >> 3) & 3) + 4 * (w & 1);
        int wlb = (w >> 1) * 4;
        float acc[4][6];
#pragma unroll
        for (int j = 0; j < 4; j++)
#pragma unroll
            for (int s = 0; s < 6; s++) acc[j][s] = 0.f;

        const float* z0p = zq + (wlb + 0) * ZQP;
        const float* z1p = zq + (wlb + 1) * ZQP;
        const float* z2p = zq + (wlb + 2) * ZQP;
        const float* z3p = zq + (wlb + 3) * ZQP;
        const float* wp = wds + (rg * 6) * WDP;
#pragma unroll 4
        for (int i = 0; i < 64; i++) {
            int d = dq + 8 * i;
            float z0 = z0p[d], z1 = z1p[d], z2 = z2p[d], z3 = z3p[d];
#pragma unroll
            for (int s = 0; s < 6; s++) {
                float wv = wp[s * WDP + d];
                acc[0][s] += z0 * wv;
                acc[1][s] += z1 * wv;
                acc[2][s] += z2 * wv;
                acc[3][s] += z3 * wv;
            }
        }
#pragma unroll
        for (int off = 1; off < 8; off <<= 1)
#pragma unroll
            for (int j = 0; j < 4; j++)
#pragma unroll
                for (int s = 0; s < 6; s++)
                    acc[j][s] += __shfl_xor_sync(0xffffffffu, acc[j][s], off);
        if (dq == 0) {
#pragma unroll
            for (int j = 0; j < 4; j++)
#pragma unroll
                for (int s = 0; s < 6; s++)
                    part[(wlb + j) * 48 + rg * 6 + s] = acc[j][s];
        }
    }
    __syncthreads();

#pragma unroll
    for (int it = 0; it < 3; it++) {
        int o = it * 512 + tid;
        int wlo = o / 48;
        int ro = o - wlo * 48;
        float v = part[wlo * 48 + ro];
        int cc = ro >> 4, ii = (ro >> 2) & 3, jj = ro & 3;
        v += bd[cc];
        float s = 1.f / (1.f + __expf(-v));
        out_recon[((b * NC + cc) * NH + (4 * hl + ii)) * NH + wlo * 4 + jj] = s;
    }
}

// ---------------- launch ----------------
extern "C" void kernel_launch(void* const* d_in, const int* in_sizes, int n_in,
                              void* d_out, int out_size) {
    const float* x  = (const float*)d_in[0];
    const float* We = (const float*)d_in[1];
    const float* be = (const float*)d_in[2];
    const float* Wd = (const float*)d_in[3];
    const float* bd = (const float*)d_in[4];
    const float* cb = (const float*)d_in[5];

    float* out = (float*)d_out;
    float* out_recon = out;
    float* out_ze    = out + RECON_N;
    float* out_emb   = out + RECON_N + ZE_N;

    const int enc_smem = (16 * 48 + 256 * 48) * sizeof(float);  // 52224
    cudaFuncSetAttribute(k_encode, cudaFuncAttributeMaxDynamicSharedMemorySize, enc_smem);
    cudaFuncSetAttribute(k_nn, cudaFuncAttributeMaxDynamicSharedMemorySize, NN_SMEM);
    cudaFuncSetAttribute(k_gde, cudaFuncAttributeMaxDynamicSharedMemorySize, GDE_SMEM);

    k_prep_cbt<<<dim3(16, 16), dim3(32, 8)>>>(cb);
    k_prep2<<<226, 256>>>(Wd);
    k_encode<<<dim3(1024, 4), 256, enc_smem>>>(x, We, be, out_ze);
    k_nn<<<dim3(256, 2), 256, NN_SMEM>>>();
    k_rescore<<<4096, 256>>>();
    k_gde<<<1024, 512, GDE_SMEM>>>(bd, out_emb, out_recon);
}

// round 12
// speedup vs baseline: 1.1504x; 1.1504x over previous
#include <cuda_runtime.h>
#include <cuda_bf16.h>
#include <cstdint>

// VQ-VAE forward on GB300 (base sm_103 target: mma.sync/ldmatrix/cp.async).
// Outputs (flattened, in order): recon (32,3,128,128), z_e (32,512,32,32), emb (32,512,32,32)

#define NB 32
#define NC 3
#define NH 128
#define ND 512
#define NK 512
#define NHL 32
#define NL 1024
#define NM (NB * NL)  // 32768

#define RECON_N (32 * 3 * 128 * 128)
#define ZE_N (32 * 512 * 32 * 32)
#define MARGIN 0.45f
#define NSLOT 16

// ---------------- scratch (static device memory; no allocations) ----------------
__device__ __nv_bfloat16 g_zh[NM * ND];   // z_e hi split, row-major (M, D)
__device__ __nv_bfloat16 g_zl[NM * ND];   // z_e lo split
__device__ __nv_bfloat16 g_cbh[NK * ND];  // codebook^T bf16 (K, D)
__device__ float g_cbt[NK * ND];          // codebook^T fp32 (K, D)
__device__ float g_w2[NK];                // ||W[:,k]||^2 (fp32 exact)
__device__ float g_wdt[48 * ND];          // decoder weights, spatial flip baked in
__device__ int   g_idx[NM];               // final argmin indices
__device__ unsigned long long g_key[NM];  // pass-1 packed (approx dist, k)
__device__ int g_ccnt[NM];                // candidate counts
__device__ unsigned long long g_cand[NM * NSLOT];  // candidate packed (dist, k)

// ---------------- small helpers ----------------
__device__ __forceinline__ unsigned mapf(float x) {
    unsigned u = __float_as_uint(x);
    return (u & 0x80000000u) ? ~u : (u | 0x80000000u);   // order-preserving
}
__device__ __forceinline__ float unmapf(unsigned m) {
    unsigned u = (m & 0x80000000u) ? (m ^ 0x80000000u) : ~m;
    return __uint_as_float(u);
}

#define CP_ASYNC16(smaddr, gptr) \
    asm volatile("cp.async.cg.shared.global [%0], [%1], 16;" :: "r"(smaddr), "l"(gptr))
#define CP_COMMIT() asm volatile("cp.async.commit_group;" ::: "memory")
#define CP_WAIT(n)  asm volatile("cp.async.wait_group %0;" :: "n"(n) : "memory")

__device__ __forceinline__ void ldsm4(uint32_t& r0, uint32_t& r1, uint32_t& r2, uint32_t& r3,
                                      uint32_t addr) {
    asm volatile("ldmatrix.sync.aligned.m8n8.x4.shared.b16 {%0,%1,%2,%3}, [%4];"
                 : "=r"(r0), "=r"(r1), "=r"(r2), "=r"(r3) : "r"(addr));
}
__device__ __forceinline__ void mma16816(float* c, const uint32_t* a, uint32_t b0, uint32_t b1) {
    asm volatile(
        "mma.sync.aligned.m16n8k16.row.col.f32.bf16.bf16.f32 "
        "{%0,%1,%2,%3}, {%4,%5,%6,%7}, {%8,%9}, {%0,%1,%2,%3};"
        : "+f"(c[0]), "+f"(c[1]), "+f"(c[2]), "+f"(c[3])
        : "r"(a[0]), "r"(a[1]), "r"(a[2]), "r"(a[3]), "r"(b0), "r"(b1));
}

// ---------------- prep 1: codebook transpose (D,K)->(K,D) + bf16 split ----------------
__global__ void k_prep_cbt(const float* __restrict__ cb) {
    __shared__ float t[32][33];
    int x = blockIdx.x * 32 + threadIdx.x;
    int y0 = blockIdx.y * 32;
    for (int r = threadIdx.y; r < 32; r += 8)
        t[r][threadIdx.x] = cb[(y0 + r) * NK + x];
    __syncthreads();
    int xo = blockIdx.y * 32 + threadIdx.x;
    int yo = blockIdx.x * 32;
    for (int r = threadIdx.y; r < 32; r += 8) {
        float v = t[threadIdx.x][r];
        g_cbt[(yo + r) * ND + xo] = v;
        g_cbh[(yo + r) * ND + xo] = __float2bfloat16(v);
    }
}

// ---------------- prep 2 (fused): wdt / w2 / key-init, range-partitioned ----------------
__global__ void k_prep2(const float* __restrict__ Wd) {
    int blk = blockIdx.x, tid = threadIdx.x;
    if (blk < 96) {
        int e = blk * 256 + tid;   // 48*512 = 24576
        int r = e >> 9, d = e & 511;
        int c = r >> 4, i = (r >> 2) & 3, j = r & 3;
        g_wdt[e] = Wd[(c * ND + d) * 16 + (3 - i) * 4 + (3 - j)];
    } else if (blk < 98) {
        int k = (blk - 96) * 256 + tid;
        const float* row = g_cbt + k * ND;
        float s = 0.f;
        for (int d = 0; d < ND; d += 4) {
            float4 v = *reinterpret_cast<const float4*>(row + d);
            s += v.x * v.x + v.y * v.y + v.z * v.z + v.w * v.w;
        }
        g_w2[k] = s;
    } else {
        int m = (blk - 98) * 256 + tid;   // 128 blocks -> 32768
        g_key[m] = 0xFFFFFFFFFFFFFFFFull;
        g_ccnt[m] = 0;
    }
}

// ---------------- encode: patch-embed GEMM + bias + relu ----------------
// grid (1024, 4): x = (b,hl); y: bit0 = position half (16 wl), bit1 = d half (256).
// We staged at pitch 257: stores (bank = q+r mod 32) and reads (bank = q+tid mod 32)
// are both conflict-free (vs old tid*48 layout: 16-way conflict x 48 loads).
#define WEP 257
__global__ __launch_bounds__(256) void k_encode(const float* __restrict__ x,
                                                const float* __restrict__ We,
                                                const float* __restrict__ be,
                                                float* __restrict__ out_ze) {
    extern __shared__ float esm[];
    float* patch = esm;           // [16][48]
    float* wsm = esm + 16 * 48;   // [48][WEP] : wsm[q*WEP + r] = We[dh*256+r][q]
    int blk = blockIdx.x;
    int b = blk >> 5, hl = blk & 31;
    int ph = blockIdx.y & 1, dh = blockIdx.y >> 1;
    int tid = threadIdx.x;

    for (int e = tid; e < 256 * 48; e += 256) {
        int r = e / 48, q = e - r * 48;
        wsm[q * WEP + r] = We[dh * (256 * 48) + e];
    }
    for (int e = tid; e < 768; e += 256) {
        int row = e >> 6, cc = e & 63;
        int c = row >> 2, i = row & 3;
        float v = x[((b * NC + c) * NH + (4 * hl + i)) * NH + ph * 64 + cc];
        patch[(cc >> 2) * 48 + c * 16 + i * 4 + (cc & 3)] = v;
    }
    __syncthreads();

    int d = dh * 256 + tid;
    float w[48];
#pragma unroll
    for (int q = 0; q < 48; q++) w[q] = wsm[q * WEP + tid];
    float bias = be[d];

    float acc[16];
    int mbase = b * NL + hl * 32 + ph * 16;
#pragma unroll
    for (int pos = 0; pos < 16; pos++) {
        float p0 = bias, p1 = 0.f, p2 = 0.f, p3 = 0.f;
        const float* pp = patch + pos * 48;
#pragma unroll
        for (int q = 0; q < 12; q++) {
            float* dst = (q & 3) == 0 ? &p0 : (q & 3) == 1 ? &p1 : (q & 3) == 2 ? &p2 : &p3;
            *dst += pp[4*q] * w[4*q] + pp[4*q+1] * w[4*q+1] + pp[4*q+2] * w[4*q+2] + pp[4*q+3] * w[4*q+3];
        }
        float v = fmaxf((p0 + p1) + (p2 + p3), 0.f);
        acc[pos] = v;
        __nv_bfloat16 h = __float2bfloat16(v);
        int zi = (mbase + pos) * ND + d;
        g_zh[zi] = h;
        g_zl[zi] = __float2bfloat16(v - __bfloat162float(h));
    }
    float4* o4 = reinterpret_cast<float4*>(out_ze + ((b * ND + d) * NHL + hl) * NHL + ph * 16);
#pragma unroll
    for (int q = 0; q < 4; q++)
        o4[q] = make_float4(acc[4*q], acc[4*q+1], acc[4*q+2], acc[4*q+3]);
}

// ---------------- pass 1: bf16 HMMA GEMM + approx argmin + candidate flagging ----------------
// Round-9 config (measured 63.0us): 128x128 block, 32x64 warp tile, 2-stage, 2 blocks/SM.
#define STG_BYTES 18432
#define NN_SMEM (4 * STG_BYTES)

__device__ __forceinline__ void nn_fill(uint32_t smb, int stg, int kc, int m0, int n0, int tid) {
    uint32_t ab = smb + stg * STG_BYTES;
    uint32_t bb = smb + 2 * STG_BYTES + stg * STG_BYTES;
#pragma unroll
    for (int i = 0; i < 4; i++) {
        int u = i * 256 + tid;
        int r = u >> 3, cg = u & 7;
        CP_ASYNC16(ab + r * 144 + cg * 16, g_zh + (m0 + r) * ND + kc * 64 + cg * 8);
    }
#pragma unroll
    for (int i = 0; i < 4; i++) {
        int u = i * 256 + tid;
        int r = u >> 3, cg = u & 7;
        CP_ASYNC16(bb + r * 144 + cg * 16, g_cbh + (n0 + r) * ND + kc * 64 + cg * 8);
    }
}

__global__ __launch_bounds__(256, 2) void k_nn() {
    extern __shared__ __align__(16) char nsm[];
    __shared__ float w2s[128];
    __shared__ unsigned rmin[128];
    int tid = threadIdx.x;
    int lane = tid & 31, wrp = tid >> 5;
    int wm = wrp & 3, wn = wrp >> 2;      // 4 x 2 warp grid; warp tile 32(m) x 64(n)
    int m0 = blockIdx.x * 128, n0 = blockIdx.y * 128;
    uint32_t smb = (uint32_t)__cvta_generic_to_shared(nsm);

    if (tid < 128) { w2s[tid] = g_w2[n0 + tid]; rmin[tid] = 0xFFFFFFFFu; }

    float cfr[2][8][4];
#pragma unroll
    for (int mt = 0; mt < 2; mt++)
#pragma unroll
        for (int nt = 0; nt < 8; nt++)
#pragma unroll
            for (int q = 0; q < 4; q++) cfr[mt][nt][q] = 0.f;

    nn_fill(smb, 0, 0, m0, n0, tid);
    CP_COMMIT();

    for (int kc = 0; kc < 8; kc++) {
        if (kc < 7) { nn_fill(smb, (kc + 1) & 1, kc + 1, m0, n0, tid); CP_COMMIT(); CP_WAIT(1); }
        else        { CP_WAIT(0); }
        __syncthreads();
        uint32_t sa = smb + (kc & 1) * STG_BYTES;
        uint32_t sb = smb + 2 * STG_BYTES + (kc & 1) * STG_BYTES;
#pragma unroll
        for (int ks = 0; ks < 4; ks++) {
            uint32_t afr[2][4];
#pragma unroll
            for (int mt = 0; mt < 2; mt++) {
                int r = wm * 32 + mt * 16 + ((lane >> 3) & 1) * 8 + (lane & 7);
                int cb = ks * 32 + (lane >> 4) * 16;
                ldsm4(afr[mt][0], afr[mt][1], afr[mt][2], afr[mt][3], sa + r * 144 + cb);
            }
            uint32_t bfr[8][2];
#pragma unroll
            for (int p = 0; p < 4; p++) {
                int r = wn * 64 + p * 16 + (lane >> 4) * 8 + (lane & 7);
                int cb = ks * 32 + ((lane >> 3) & 1) * 16;
                uint32_t b0, b1, b2, b3;
                ldsm4(b0, b1, b2, b3, sb + r * 144 + cb);
                bfr[2*p][0] = b0; bfr[2*p][1] = b1; bfr[2*p+1][0] = b2; bfr[2*p+1][1] = b3;
            }
#pragma unroll
            for (int mt = 0; mt < 2; mt++)
#pragma unroll
                for (int nt = 0; nt < 8; nt++)
                    mma16816(cfr[mt][nt], afr[mt], bfr[nt][0], bfr[nt][1]);
        }
        __syncthreads();
    }

    // epilogue phase 1: per-row block min (smem) + global packed atomicMin
#pragma unroll
    for (int mt = 0; mt < 2; mt++) {
#pragma unroll
        for (int h = 0; h < 2; h++) {
            int lr = wm * 32 + mt * 16 + (lane >> 2) + h * 8;
            unsigned long long best = 0xFFFFFFFFFFFFFFFFull;
#pragma unroll
            for (int nt = 0; nt < 8; nt++)
#pragma unroll
                for (int c2 = 0; c2 < 2; c2++) {
                    int kl = wn * 64 + nt * 8 + (lane & 3) * 2 + c2;
                    float dist = w2s[kl] - 2.f * cfr[mt][nt][h * 2 + c2];
                    unsigned long long key =
                        ((unsigned long long)mapf(dist) << 32) | (unsigned)(n0 + kl);
                    if (key < best) best = key;
                }
            unsigned long long o1 = __shfl_xor_sync(0xffffffffu, best, 1);
            if (o1 < best) best = o1;
            unsigned long long o2 = __shfl_xor_sync(0xffffffffu, best, 2);
            if (o2 < best) best = o2;
            if ((lane & 3) == 0) {
                atomicMin(&rmin[lr], (unsigned)(best >> 32));
                atomicMin(&g_key[m0 + lr], best);
            }
        }
    }
    __syncthreads();

    // epilogue phase 2: flag candidates (store packed key) within MARGIN of block row-min
#pragma unroll
    for (int mt = 0; mt < 2; mt++) {
#pragma unroll
        for (int h = 0; h < 2; h++) {
            int lr = wm * 32 + mt * 16 + (lane >> 2) + h * 8;
            float thr = unmapf(rmin[lr]) + MARGIN;
#pragma unroll
            for (int nt = 0; nt < 8; nt++)
#pragma unroll
                for (int c2 = 0; c2 < 2; c2++) {
                    int kl = wn * 64 + nt * 8 + (lane & 3) * 2 + c2;
                    float dist = w2s[kl] - 2.f * cfr[mt][nt][h * 2 + c2];
                    if (dist <= thr) {
                        int pos = atomicAdd(&g_ccnt[m0 + lr], 1);
                        if (pos < NSLOT)
                            g_cand[(m0 + lr) * NSLOT + pos] =
                                ((unsigned long long)mapf(dist) << 32) | (unsigned)(n0 + kl);
                    }
                }
        }
    }
}

// ---------------- pass 2: exact fp32 rescore (fast path: approx winner unambiguous) ----------------
__global__ __launch_bounds__(256) void k_rescore() {
    int tid = threadIdx.x, lane = tid & 31;
    int m = blockIdx.x * 8 + (tid >> 5);

    unsigned long long gkey = g_key[m];
    float amin = unmapf((unsigned)(gkey >> 32));
    int kstar = (int)(gkey & 0xFFFFFFFFu);
    int cnt = g_ccnt[m]; if (cnt > NSLOT) cnt = NSLOT;

    unsigned long long ck = 0xFFFFFFFFFFFFFFFFull;
    if (lane < cnt) ck = g_cand[m * NSLOT + lane];
    bool qual = (lane < cnt) && (ck != gkey) &&
                (unmapf((unsigned)(ck >> 32)) <= amin + MARGIN);
    unsigned bal = __ballot_sync(0xffffffffu, qual);
    if (bal == 0) {   // no challenger within global margin: approx winner is exact
        if (lane == 0) g_idx[m] = kstar;
        return;
    }

    // slow path: reconstruct z (fp32 from hi+lo) and exactly rescore kstar + challengers
    float4 z[4];
#pragma unroll
    for (int t = 0; t < 4; t++) {
        int d = t * 128 + lane * 4;
        uint2 hh = *reinterpret_cast<const uint2*>(g_zh + m * ND + d);
        uint2 ll = *reinterpret_cast<const uint2*>(g_zl + m * ND + d);
        __nv_bfloat162 h0 = *reinterpret_cast<__nv_bfloat162*>(&hh.x);
        __nv_bfloat162 h1 = *reinterpret_cast<__nv_bfloat162*>(&hh.y);
        __nv_bfloat162 l0 = *reinterpret_cast<__nv_bfloat162*>(&ll.x);
        __nv_bfloat162 l1 = *reinterpret_cast<__nv_bfloat162*>(&ll.y);
        z[t].x = __bfloat162float(h0.x) + __bfloat162float(l0.x);
        z[t].y = __bfloat162float(h0.y) + __bfloat162float(l0.y);
        z[t].z = __bfloat162float(h1.x) + __bfloat162float(l1.x);
        z[t].w = __bfloat162float(h1.y) + __bfloat162float(l1.y);
    }
    unsigned mycand = (unsigned)(ck & 0xFFFFFFFFu);
    unsigned long long best = 0xFFFFFFFFFFFFFFFFull;
    int k = kstar;
    unsigned rem = bal;
    for (;;) {
        float s = 0.f;
#pragma unroll
        for (int t = 0; t < 4; t++) {
            float4 cv = *reinterpret_cast<const float4*>(g_cbt + k * ND + t * 128 + lane * 4);
            s += z[t].x * cv.x + z[t].y * cv.y + z[t].z * cv.z + z[t].w * cv.w;
        }
#pragma unroll
        for (int off = 16; off > 0; off >>= 1) s += __shfl_xor_sync(0xffffffffu, s, off);
        float dist = g_w2[k] - 2.f * s;
        unsigned long long key = ((unsigned long long)mapf(dist) << 32) | (unsigned)k;
        if (key < best) best = key;
        if (!rem) break;
        int src = __ffs(rem) - 1;
        rem &= rem - 1;
        k = (int)__shfl_sync(0xffffffffu, mycand, src);
    }
    if (lane == 0) g_idx[m] = (int)(best & 0xFFFFFFFFu);
}

// ---------------- gather (emb) + decode (recon) ----------------
// zq pitch 517 (conflict-free broadcast), wds pitch 524 (conflict-free row groups).
#define ZQP 517
#define WDP 524
#define GDE_SMEM ((32 * ZQP + 48 * WDP + 1536) * 4)
__global__ __launch_bounds__(512) void k_gde(const float* __restrict__ bd,
                                             float* __restrict__ out_emb,
                                             float* __restrict__ out_recon) {
    extern __shared__ float smf[];
    float* zq = smf;                       // [32][ZQP]
    float* wds = smf + 32 * ZQP;           // [48][WDP]
    float* part = smf + 32 * ZQP + 48 * WDP;  // [32*48]
    __shared__ int karr[32];

    int blk = blockIdx.x;
    int b = blk >> 5, hl = blk & 31;
    int tid = threadIdx.x;

    if (tid < 32) karr[tid] = g_idx[b * NL + hl * 32 + tid];
    for (int e = tid; e < 48 * ND; e += 512) {
        int r = e >> 9, d = e & 511;
        wds[r * WDP + d] = g_wdt[e];
    }
    __syncthreads();
    for (int e = tid; e < 32 * ND; e += 512) {
        int wl = e >> 9, d = e & 511;
        zq[wl * ZQP + d] = g_cbt[karr[wl] * ND + d];
    }
    __syncthreads();

    // emb output (B,D,L)
    float* eb = out_emb + b * (ND * NL) + hl * 32;
    for (int e = tid; e < 16384; e += 512) {
        int d = e >> 5, wl = e & 31;
        eb[d * NL + wl] = zq[wl * ZQP + d];
    }

    // decode: register-tiled 4(wl) x 6(r) per thread, d interleaved stride 8.
    {
        int lane = tid & 31, w = tid >> 5;
        int dq = lane & 7;
        int rg = ((lane >> 3) & 3) + 4 * (w & 1);
        int wlb = (w >> 1) * 4;
        float acc[4][6];
#pragma unroll
        for (int j = 0; j < 4; j++)
#pragma unroll
            for (int s = 0; s < 6; s++) acc[j][s] = 0.f;

        const float* z0p = zq + (wlb + 0) * ZQP;
        const float* z1p = zq + (wlb + 1) * ZQP;
        const float* z2p = zq + (wlb + 2) * ZQP;
        const float* z3p = zq + (wlb + 3) * ZQP;
        const float* wp = wds + (rg * 6) * WDP;
#pragma unroll 4
        for (int i = 0; i < 64; i++) {
            int d = dq + 8 * i;
            float z0 = z0p[d], z1 = z1p[d], z2 = z2p[d], z3 = z3p[d];
#pragma unroll
            for (int s = 0; s < 6; s++) {
                float wv = wp[s * WDP + d];
                acc[0][s] += z0 * wv;
                acc[1][s] += z1 * wv;
                acc[2][s] += z2 * wv;
                acc[3][s] += z3 * wv;
            }
        }
#pragma unroll
        for (int off = 1; off < 8; off <<= 1)
#pragma unroll
            for (int j = 0; j < 4; j++)
#pragma unroll
                for (int s = 0; s < 6; s++)
                    acc[j][s] += __shfl_xor_sync(0xffffffffu, acc[j][s], off);
        if (dq == 0) {
#pragma unroll
            for (int j = 0; j < 4; j++)
#pragma unroll
                for (int s = 0; s < 6; s++)
                    part[(wlb + j) * 48 + rg * 6 + s] = acc[j][s];
        }
    }
    __syncthreads();

#pragma unroll
    for (int it = 0; it < 3; it++) {
        int o = it * 512 + tid;
        int wlo = o / 48;
        int ro = o - wlo * 48;
        float v = part[wlo * 48 + ro];
        int cc = ro >> 4, ii = (ro >> 2) & 3, jj = ro & 3;
        v += bd[cc];
        float s = 1.f / (1.f + __expf(-v));
        out_recon[((b * NC + cc) * NH + (4 * hl + ii)) * NH + wlo * 4 + jj] = s;
    }
}

// ---------------- launch ----------------
extern "C" void kernel_launch(void* const* d_in, const int* in_sizes, int n_in,
                              void* d_out, int out_size) {
    const float* x  = (const float*)d_in[0];
    const float* We = (const float*)d_in[1];
    const float* be = (const float*)d_in[2];
    const float* Wd = (const float*)d_in[3];
    const float* bd = (const float*)d_in[4];
    const float* cb = (const float*)d_in[5];

    float* out = (float*)d_out;
    float* out_recon = out;
    float* out_ze    = out + RECON_N;
    float* out_emb   = out + RECON_N + ZE_N;

    const int enc_smem = (16 * 48 + 48 * WEP) * sizeof(float);  // 52416
    cudaFuncSetAttribute(k_encode, cudaFuncAttributeMaxDynamicSharedMemorySize, enc_smem);
    cudaFuncSetAttribute(k_nn, cudaFuncAttributeMaxDynamicSharedMemorySize, NN_SMEM);
    cudaFuncSetAttribute(k_gde, cudaFuncAttributeMaxDynamicSharedMemorySize, GDE_SMEM);

    k_prep_cbt<<<dim3(16, 16), dim3(32, 8)>>>(cb);
    k_prep2<<<226, 256>>>(Wd);
    k_encode<<<dim3(1024, 4), 256, enc_smem>>>(x, We, be, out_ze);
    k_nn<<<dim3(256, 4), 256, NN_SMEM>>>();
    k_rescore<<<4096, 256>>>();
    k_gde<<<1024, 512, GDE_SMEM>>>(bd, out_emb, out_recon);
}

// round 13
// speedup vs baseline: 1.1583x; 1.0069x over previous
#include <cuda_runtime.h>
#include <cuda_bf16.h>
#include <cstdint>

// VQ-VAE forward on GB300 (base sm_103 target: mma.sync/ldmatrix/cp.async).
// Outputs (flattened, in order): recon (32,3,128,128), z_e (32,512,32,32), emb (32,512,32,32)

#define NB 32
#define NC 3
#define NH 128
#define ND 512
#define NK 512
#define NHL 32
#define NL 1024
#define NM (NB * NL)  // 32768

#define RECON_N (32 * 3 * 128 * 128)
#define ZE_N (32 * 512 * 32 * 32)
#define MARGIN 0.45f
#define NSLOT 16

// ---------------- scratch (static device memory; no allocations) ----------------
__device__ __nv_bfloat16 g_zh[NM * ND];   // z_e hi split, row-major (M, D)
__device__ __nv_bfloat16 g_zl[NM * ND];   // z_e lo split
__device__ __nv_bfloat16 g_cbh[NK * ND];  // codebook^T bf16 (K, D)
__device__ float g_cbt[NK * ND];          // codebook^T fp32 (K, D)
__device__ float g_w2[NK];                // ||W[:,k]||^2 (fp32 exact)
__device__ float g_wdt[48 * ND];          // decoder weights, spatial flip baked in
__device__ int   g_idx[NM];               // final argmin indices
__device__ unsigned long long g_key[NM];  // pass-1 packed (approx dist, k)
__device__ int g_ccnt[NM];                // candidate counts
__device__ unsigned long long g_cand[NM * NSLOT];  // candidate packed (dist, k)

// ---------------- small helpers ----------------
__device__ __forceinline__ unsigned mapf(float x) {
    unsigned u = __float_as_uint(x);
    return (u & 0x80000000u) ? ~u : (u | 0x80000000u);   // order-preserving
}
__device__ __forceinline__ float unmapf(unsigned m) {
    unsigned u = (m & 0x80000000u) ? (m ^ 0x80000000u) : ~m;
    return __uint_as_float(u);
}

#define CP_ASYNC16(smaddr, gptr) \
    asm volatile("cp.async.cg.shared.global [%0], [%1], 16;" :: "r"(smaddr), "l"(gptr))
#define CP_COMMIT() asm volatile("cp.async.commit_group;" ::: "memory")
#define CP_WAIT(n)  asm volatile("cp.async.wait_group %0;" :: "n"(n) : "memory")

__device__ __forceinline__ void ldsm4(uint32_t& r0, uint32_t& r1, uint32_t& r2, uint32_t& r3,
                                      uint32_t addr) {
    asm volatile("ldmatrix.sync.aligned.m8n8.x4.shared.b16 {%0,%1,%2,%3}, [%4];"
                 : "=r"(r0), "=r"(r1), "=r"(r2), "=r"(r3) : "r"(addr));
}
__device__ __forceinline__ void mma16816(float* c, const uint32_t* a, uint32_t b0, uint32_t b1) {
    asm volatile(
        "mma.sync.aligned.m16n8k16.row.col.f32.bf16.bf16.f32 "
        "{%0,%1,%2,%3}, {%4,%5,%6,%7}, {%8,%9}, {%0,%1,%2,%3};"
        : "+f"(c[0]), "+f"(c[1]), "+f"(c[2]), "+f"(c[3])
        : "r"(a[0]), "r"(a[1]), "r"(a[2]), "r"(a[3]), "r"(b0), "r"(b1));
}

// ---------------- fused prep + encode ----------------
// grid: [0,256)   codebook transpose (D,K)->(K,D) + bf16
//       [256,482) wdt flip / w2 (from cb directly) / key+ccnt init
//       [482,4578) encode: patch-embed GEMM + bias + relu
#define WEP 257
#define ENC_SMEM ((16 * 48 + 48 * WEP) * 4)   // 52416 B

__global__ __launch_bounds__(256) void k_prep_encode(const float* __restrict__ x,
                                                     const float* __restrict__ We,
                                                     const float* __restrict__ be,
                                                     const float* __restrict__ Wd,
                                                     const float* __restrict__ cb,
                                                     float* __restrict__ out_ze) {
    int bid = blockIdx.x;
    int tid = threadIdx.x;

    if (bid < 256) {   // codebook transpose
        __shared__ float t[32][33];
        int bx = bid & 15, by = bid >> 4;
        int tx = tid & 31, ty = tid >> 5;
        int xx = bx * 32 + tx;
        int y0 = by * 32;
        for (int r = ty; r < 32; r += 8)
            t[r][tx] = cb[(y0 + r) * NK + xx];
        __syncthreads();
        int xo = by * 32 + tx;
        int yo = bx * 32;
        for (int r = ty; r < 32; r += 8) {
            float v = t[tx][r];
            g_cbt[(yo + r) * ND + xo] = v;
            g_cbh[(yo + r) * ND + xo] = __float2bfloat16(v);
        }
        return;
    }
    if (bid < 482) {   // wdt / w2 / init
        int blk = bid - 256;
        if (blk < 96) {
            int e = blk * 256 + tid;
            int r = e >> 9, d = e & 511;
            int c = r >> 4, i = (r >> 2) & 3, j = r & 3;
            g_wdt[e] = Wd[(c * ND + d) * 16 + (3 - i) * 4 + (3 - j)];
        } else if (blk < 98) {
            int k = (blk - 96) * 256 + tid;
            float s = 0.f;
            for (int d = 0; d < ND; d++) {
                float v = cb[d * NK + k];   // coalesced across tid
                s += v * v;
            }
            g_w2[k] = s;
        } else {
            int m = (blk - 98) * 256 + tid;   // 128 blocks -> 32768
            g_key[m] = 0xFFFFFFFFFFFFFFFFull;
            g_ccnt[m] = 0;
        }
        return;
    }

    // ---- encode ----
    extern __shared__ float esm[];
    float* patch = esm;           // [16][48]
    float* wsm = esm + 16 * 48;   // [48][WEP]
    int e_blk = bid - 482;
    int blk = e_blk & 1023;
    int yy = e_blk >> 10;
    int b = blk >> 5, hl = blk & 31;
    int ph = yy & 1, dh = yy >> 1;

    for (int e = tid; e < 256 * 48; e += 256) {
        int r = e / 48, q = e - r * 48;
        wsm[q * WEP + r] = We[dh * (256 * 48) + e];
    }
    for (int e = tid; e < 768; e += 256) {
        int row = e >> 6, cc = e & 63;
        int c = row >> 2, i = row & 3;
        float v = x[((b * NC + c) * NH + (4 * hl + i)) * NH + ph * 64 + cc];
        patch[(cc >> 2) * 48 + c * 16 + i * 4 + (cc & 3)] = v;
    }
    __syncthreads();

    int d = dh * 256 + tid;
    float w[48];
#pragma unroll
    for (int q = 0; q < 48; q++) w[q] = wsm[q * WEP + tid];
    float bias = be[d];

    float acc[16];
    int mbase = b * NL + hl * 32 + ph * 16;
#pragma unroll
    for (int pos = 0; pos < 16; pos++) {
        float p0 = bias, p1 = 0.f, p2 = 0.f, p3 = 0.f;
        const float* pp = patch + pos * 48;
#pragma unroll
        for (int q = 0; q < 12; q++) {
            float* dst = (q & 3) == 0 ? &p0 : (q & 3) == 1 ? &p1 : (q & 3) == 2 ? &p2 : &p3;
            *dst += pp[4*q] * w[4*q] + pp[4*q+1] * w[4*q+1] + pp[4*q+2] * w[4*q+2] + pp[4*q+3] * w[4*q+3];
        }
        float v = fmaxf((p0 + p1) + (p2 + p3), 0.f);
        acc[pos] = v;
        __nv_bfloat16 h = __float2bfloat16(v);
        int zi = (mbase + pos) * ND + d;
        g_zh[zi] = h;
        g_zl[zi] = __float2bfloat16(v - __bfloat162float(h));
    }
    float4* o4 = reinterpret_cast<float4*>(out_ze + ((b * ND + d) * NHL + hl) * NHL + ph * 16);
#pragma unroll
    for (int q = 0; q < 4; q++)
        o4[q] = make_float4(acc[4*q], acc[4*q+1], acc[4*q+2], acc[4*q+3]);
}

// ---------------- pass 1: bf16 HMMA GEMM + approx argmin + candidate flagging ----------------
// Block tile 128x128; 128 threads = 4 warps in 2(m) x 2(n) grid; warp tile 64x64.
// 2-stage cp.async double-buffer; 2 blocks/SM (cross-block bubble overlap).
// ldsm redundancy: A x2 + B x2 = 64 KB/block/kc (vs 96 KB at 32x64 tiles) ->
// smem ~1600 cyc < tensor 2048 cyc per SM per kc: tensor-bound.
#define STG_BYTES 18432
#define NN_SMEM (4 * STG_BYTES)   // 73728 B

__device__ __forceinline__ void nn_fill(uint32_t smb, int stg, int kc, int m0, int n0, int tid) {
    uint32_t ab = smb + stg * STG_BYTES;
    uint32_t bb = smb + 2 * STG_BYTES + stg * STG_BYTES;
#pragma unroll
    for (int i = 0; i < 8; i++) {
        int u = i * 128 + tid;            // 0..1023
        int r = u >> 3, cg = u & 7;
        CP_ASYNC16(ab + r * 144 + cg * 16, g_zh + (m0 + r) * ND + kc * 64 + cg * 8);
    }
#pragma unroll
    for (int i = 0; i < 8; i++) {
        int u = i * 128 + tid;
        int r = u >> 3, cg = u & 7;
        CP_ASYNC16(bb + r * 144 + cg * 16, g_cbh + (n0 + r) * ND + kc * 64 + cg * 8);
    }
}

__global__ __launch_bounds__(128, 2) void k_nn() {
    extern __shared__ __align__(16) char nsm[];
    __shared__ float w2s[128];
    __shared__ unsigned rmin[128];
    int tid = threadIdx.x;
    int lane = tid & 31, wrp = tid >> 5;
    int wm = wrp & 1, wn = wrp >> 1;      // 2 x 2 warp grid; warp tile 64(m) x 64(n)
    int m0 = blockIdx.x * 128, n0 = blockIdx.y * 128;
    uint32_t smb = (uint32_t)__cvta_generic_to_shared(nsm);

    if (tid < 128) { w2s[tid] = g_w2[n0 + tid]; rmin[tid] = 0xFFFFFFFFu; }

    float cfr[4][8][4];
#pragma unroll
    for (int mt = 0; mt < 4; mt++)
#pragma unroll
        for (int nt = 0; nt < 8; nt++)
#pragma unroll
            for (int q = 0; q < 4; q++) cfr[mt][nt][q] = 0.f;

    nn_fill(smb, 0, 0, m0, n0, tid);
    CP_COMMIT();

    for (int kc = 0; kc < 8; kc++) {
        if (kc < 7) { nn_fill(smb, (kc + 1) & 1, kc + 1, m0, n0, tid); CP_COMMIT(); CP_WAIT(1); }
        else        { CP_WAIT(0); }
        __syncthreads();
        uint32_t sa = smb + (kc & 1) * STG_BYTES;
        uint32_t sb = smb + 2 * STG_BYTES + (kc & 1) * STG_BYTES;
#pragma unroll
        for (int ks = 0; ks < 4; ks++) {
            uint32_t afr[4][4];
#pragma unroll
            for (int mt = 0; mt < 4; mt++) {
                int r = wm * 64 + mt * 16 + ((lane >> 3) & 1) * 8 + (lane & 7);
                int cb = ks * 32 + (lane >> 4) * 16;
                ldsm4(afr[mt][0], afr[mt][1], afr[mt][2], afr[mt][3], sa + r * 144 + cb);
            }
            uint32_t bfr[8][2];
#pragma unroll
            for (int p = 0; p < 4; p++) {
                int r = wn * 64 + p * 16 + (lane >> 4) * 8 + (lane & 7);
                int cb = ks * 32 + ((lane >> 3) & 1) * 16;
                uint32_t b0, b1, b2, b3;
                ldsm4(b0, b1, b2, b3, sb + r * 144 + cb);
                bfr[2*p][0] = b0; bfr[2*p][1] = b1; bfr[2*p+1][0] = b2; bfr[2*p+1][1] = b3;
            }
#pragma unroll
            for (int mt = 0; mt < 4; mt++)
#pragma unroll
                for (int nt = 0; nt < 8; nt++)
                    mma16816(cfr[mt][nt], afr[mt], bfr[nt][0], bfr[nt][1]);
        }
        __syncthreads();
    }

    // epilogue phase 1: per-row block min (smem) + global packed atomicMin
#pragma unroll
    for (int mt = 0; mt < 4; mt++) {
#pragma unroll
        for (int h = 0; h < 2; h++) {
            int lr = wm * 64 + mt * 16 + (lane >> 2) + h * 8;
            unsigned long long best = 0xFFFFFFFFFFFFFFFFull;
#pragma unroll
            for (int nt = 0; nt < 8; nt++)
#pragma unroll
                for (int c2 = 0; c2 < 2; c2++) {
                    int kl = wn * 64 + nt * 8 + (lane & 3) * 2 + c2;
                    float dist = w2s[kl] - 2.f * cfr[mt][nt][h * 2 + c2];
                    unsigned long long key =
                        ((unsigned long long)mapf(dist) << 32) | (unsigned)(n0 + kl);
                    if (key < best) best = key;
                }
            unsigned long long o1 = __shfl_xor_sync(0xffffffffu, best, 1);
            if (o1 < best) best = o1;
            unsigned long long o2 = __shfl_xor_sync(0xffffffffu, best, 2);
            if (o2 < best) best = o2;
            if ((lane & 3) == 0) {
                atomicMin(&rmin[lr], (unsigned)(best >> 32));
                atomicMin(&g_key[m0 + lr], best);
            }
        }
    }
    __syncthreads();

    // epilogue phase 2: flag candidates (store packed key) within MARGIN of block row-min
#pragma unroll
    for (int mt = 0; mt < 4; mt++) {
#pragma unroll
        for (int h = 0; h < 2; h++) {
            int lr = wm * 64 + mt * 16 + (lane >> 2) + h * 8;
            float thr = unmapf(rmin[lr]) + MARGIN;
#pragma unroll
            for (int nt = 0; nt < 8; nt++)
#pragma unroll
                for (int c2 = 0; c2 < 2; c2++) {
                    int kl = wn * 64 + nt * 8 + (lane & 3) * 2 + c2;
                    float dist = w2s[kl] - 2.f * cfr[mt][nt][h * 2 + c2];
                    if (dist <= thr) {
                        int pos = atomicAdd(&g_ccnt[m0 + lr], 1);
                        if (pos < NSLOT)
                            g_cand[(m0 + lr) * NSLOT + pos] =
                                ((unsigned long long)mapf(dist) << 32) | (unsigned)(n0 + kl);
                    }
                }
        }
    }
}

// ---------------- pass 2: exact fp32 rescore (fast path: approx winner unambiguous) ----------------
__global__ __launch_bounds__(256) void k_rescore() {
    int tid = threadIdx.x, lane = tid & 31;
    int m = blockIdx.x * 8 + (tid >> 5);

    unsigned long long gkey = g_key[m];
    float amin = unmapf((unsigned)(gkey >> 32));
    int kstar = (int)(gkey & 0xFFFFFFFFu);
    int cnt = g_ccnt[m]; if (cnt > NSLOT) cnt = NSLOT;

    unsigned long long ck = 0xFFFFFFFFFFFFFFFFull;
    if (lane < cnt) ck = g_cand[m * NSLOT + lane];
    bool qual = (lane < cnt) && (ck != gkey) &&
                (unmapf((unsigned)(ck >> 32)) <= amin + MARGIN);
    unsigned bal = __ballot_sync(0xffffffffu, qual);
    if (bal == 0) {   // no challenger within global margin: approx winner is exact
        if (lane == 0) g_idx[m] = kstar;
        return;
    }

    // slow path: reconstruct z (fp32 from hi+lo) and exactly rescore kstar + challengers
    float4 z[4];
#pragma unroll
    for (int t = 0; t < 4; t++) {
        int d = t * 128 + lane * 4;
        uint2 hh = *reinterpret_cast<const uint2*>(g_zh + m * ND + d);
        uint2 ll = *reinterpret_cast<const uint2*>(g_zl + m * ND + d);
        __nv_bfloat162 h0 = *reinterpret_cast<__nv_bfloat162*>(&hh.x);
        __nv_bfloat162 h1 = *reinterpret_cast<__nv_bfloat162*>(&hh.y);
        __nv_bfloat162 l0 = *reinterpret_cast<__nv_bfloat162*>(&ll.x);
        __nv_bfloat162 l1 = *reinterpret_cast<__nv_bfloat162*>(&ll.y);
        z[t].x = __bfloat162float(h0.x) + __bfloat162float(l0.x);
        z[t].y = __bfloat162float(h0.y) + __bfloat162float(l0.y);
        z[t].z = __bfloat162float(h1.x) + __bfloat162float(l1.x);
        z[t].w = __bfloat162float(h1.y) + __bfloat162float(l1.y);
    }
    unsigned mycand = (unsigned)(ck & 0xFFFFFFFFu);
    unsigned long long best = 0xFFFFFFFFFFFFFFFFull;
    int k = kstar;
    unsigned rem = bal;
    for (;;) {
        float s = 0.f;
#pragma unroll
        for (int t = 0; t < 4; t++) {
            float4 cv = *reinterpret_cast<const float4*>(g_cbt + k * ND + t * 128 + lane * 4);
            s += z[t].x * cv.x + z[t].y * cv.y + z[t].z * cv.z + z[t].w * cv.w;
        }
#pragma unroll
        for (int off = 16; off > 0; off >>= 1) s += __shfl_xor_sync(0xffffffffu, s, off);
        float dist = g_w2[k] - 2.f * s;
        unsigned long long key = ((unsigned long long)mapf(dist) << 32) | (unsigned)k;
        if (key < best) best = key;
        if (!rem) break;
        int src = __ffs(rem) - 1;
        rem &= rem - 1;
        k = (int)__shfl_sync(0xffffffffu, mycand, src);
    }
    if (lane == 0) g_idx[m] = (int)(best & 0xFFFFFFFFu);
}

// ---------------- gather (emb) + decode (recon) ----------------
// zq pitch 517 (conflict-free broadcast), wds pitch 524 (conflict-free row groups).
#define ZQP 517
#define WDP 524
#define GDE_SMEM ((32 * ZQP + 48 * WDP + 1536) * 4)
__global__ __launch_bounds__(512) void k_gde(const float* __restrict__ bd,
                                             float* __restrict__ out_emb,
                                             float* __restrict__ out_recon) {
    extern __shared__ float smf[];
    float* zq = smf;                       // [32][ZQP]
    float* wds = smf + 32 * ZQP;           // [48][WDP]
    float* part = smf + 32 * ZQP + 48 * WDP;  // [32*48]
    __shared__ int karr[32];

    int blk = blockIdx.x;
    int b = blk >> 5, hl = blk & 31;
    int tid = threadIdx.x;

    if (tid < 32) karr[tid] = g_idx[b * NL + hl * 32 + tid];
    for (int e = tid; e < 48 * ND; e += 512) {
        int r = e >> 9, d = e & 511;
        wds[r * WDP + d] = g_wdt[e];
    }
    __syncthreads();
    for (int e = tid; e < 32 * ND; e += 512) {
        int wl = e >> 9, d = e & 511;
        zq[wl * ZQP + d] = g_cbt[karr[wl] * ND + d];
    }
    __syncthreads();

    // emb output (B,D,L)
    float* eb = out_emb + b * (ND * NL) + hl * 32;
    for (int e = tid; e < 16384; e += 512) {
        int d = e >> 5, wl = e & 31;
        eb[d * NL + wl] = zq[wl * ZQP + d];
    }

    // decode: register-tiled 4(wl) x 6(r) per thread, d interleaved stride 8.
    {
        int lane = tid & 31, w = tid >> 5;
        int dq = lane & 7;
        int rg = ((lane >> 3) & 3) + 4 * (w & 1);
        int wlb = (w >> 1) * 4;
        float acc[4][6];
#pragma unroll
        for (int j = 0; j < 4; j++)
#pragma unroll
            for (int s = 0; s < 6; s++) acc[j][s] = 0.f;

        const float* z0p = zq + (wlb + 0) * ZQP;
        const float* z1p = zq + (wlb + 1) * ZQP;
        const float* z2p = zq + (wlb + 2) * ZQP;
        const float* z3p = zq + (wlb + 3) * ZQP;
        const float* wp = wds + (rg * 6) * WDP;
#pragma unroll 4
        for (int i = 0; i < 64; i++) {
            int d = dq + 8 * i;
            float z0 = z0p[d], z1 = z1p[d], z2 = z2p[d], z3 = z3p[d];
#pragma unroll
            for (int s = 0; s < 6; s++) {
                float wv = wp[s * WDP + d];
                acc[0][s] += z0 * wv;
                acc[1][s] += z1 * wv;
                acc[2][s] += z2 * wv;
                acc[3][s] += z3 * wv;
            }
        }
#pragma unroll
        for (int off = 1; off < 8; off <<= 1)
#pragma unroll
            for (int j = 0; j < 4; j++)
#pragma unroll
                for (int s = 0; s < 6; s++)
                    acc[j][s] += __shfl_xor_sync(0xffffffffu, acc[j][s], off);
        if (dq == 0) {
#pragma unroll
            for (int j = 0; j < 4; j++)
#pragma unroll
                for (int s = 0; s < 6; s++)
                    part[(wlb + j) * 48 + rg * 6 + s] = acc[j][s];
        }
    }
    __syncthreads();

#pragma unroll
    for (int it = 0; it < 3; it++) {
        int o = it * 512 + tid;
        int wlo = o / 48;
        int ro = o - wlo * 48;
        float v = part[wlo * 48 + ro];
        int cc = ro >> 4, ii = (ro >> 2) & 3, jj = ro & 3;
        v += bd[cc];
        float s = 1.f / (1.f + __expf(-v));
        out_recon[((b * NC + cc) * NH + (4 * hl + ii)) * NH + wlo * 4 + jj] = s;
    }
}

// ---------------- launch ----------------
extern "C" void kernel_launch(void* const* d_in, const int* in_sizes, int n_in,
                              void* d_out, int out_size) {
    const float* x  = (const float*)d_in[0];
    const float* We = (const float*)d_in[1];
    const float* be = (const float*)d_in[2];
    const float* Wd = (const float*)d_in[3];
    const float* bd = (const float*)d_in[4];
    const float* cb = (const float*)d_in[5];

    float* out = (float*)d_out;
    float* out_recon = out;
    float* out_ze    = out + RECON_N;
    float* out_emb   = out + RECON_N + ZE_N;

    cudaFuncSetAttribute(k_prep_encode, cudaFuncAttributeMaxDynamicSharedMemorySize, ENC_SMEM);
    cudaFuncSetAttribute(k_nn, cudaFuncAttributeMaxDynamicSharedMemorySize, NN_SMEM);
    cudaFuncSetAttribute(k_gde, cudaFuncAttributeMaxDynamicSharedMemorySize, GDE_SMEM);

    k_prep_encode<<<4578, 256, ENC_SMEM>>>(x, We, be, Wd, cb, out_ze);
    k_nn<<<dim3(256, 4), 128, NN_SMEM>>>();
    k_rescore<<<4096, 256>>>();
    k_gde<<<1024, 512, GDE_SMEM>>>(bd, out_emb, out_recon);
}

// round 15
// speedup vs baseline: 1.2135x; 1.0476x over previous
#include <cuda_runtime.h>
#include <cuda_bf16.h>
#include <cstdint>

// VQ-VAE forward on GB300 (base sm_103 target: mma.sync/ldmatrix/cp.async).
// Outputs (flattened, in order): recon (32,3,128,128), z_e (32,512,32,32), emb (32,512,32,32)

#define NB 32
#define NC 3
#define NH 128
#define ND 512
#define NK 512
#define NHL 32
#define NL 1024
#define NM (NB * NL)  // 32768

#define RECON_N (32 * 3 * 128 * 128)
#define ZE_N (32 * 512 * 32 * 32)
#define MARGIN 0.45f
#define NSLOT 16

// ---------------- scratch (static device memory; no allocations) ----------------
__device__ __nv_bfloat16 g_zh[NM * ND];   // z_e hi split, row-major (M, D)
__device__ __nv_bfloat16 g_zl[NM * ND];   // z_e lo split
__device__ __nv_bfloat16 g_cbh[NK * ND];  // codebook^T bf16 (K, D)
__device__ float g_cbt[NK * ND];          // codebook^T fp32 (K, D)
__device__ float g_w2[NK];                // ||W[:,k]||^2 (fp32 exact)
__device__ float g_wdt[48 * ND];          // decoder weights, spatial flip baked in
__device__ float g_P[NK * 48];            // precomputed decode: P[k][r] = wdt[r].cbt[k]
__device__ int   g_idx[NM];               // final argmin indices
__device__ unsigned long long g_key[NM];  // pass-1 packed (approx dist, k)
__device__ int g_ccnt[NM];                // candidate counts
__device__ unsigned long long g_cand[NM * NSLOT];  // candidate packed (dist, k)

// ---------------- small helpers ----------------
__device__ __forceinline__ unsigned mapf(float x) {
    unsigned u = __float_as_uint(x);
    return (u & 0x80000000u) ? ~u : (u | 0x80000000u);   // order-preserving
}
__device__ __forceinline__ float unmapf(unsigned m) {
    unsigned u = (m & 0x80000000u) ? (m ^ 0x80000000u) : ~m;
    return __uint_as_float(u);
}

#define CP_ASYNC16(smaddr, gptr) \
    asm volatile("cp.async.cg.shared.global [%0], [%1], 16;" :: "r"(smaddr), "l"(gptr))
#define CP_COMMIT() asm volatile("cp.async.commit_group;" ::: "memory")
#define CP_WAIT(n)  asm volatile("cp.async.wait_group %0;" :: "n"(n) : "memory")

__device__ __forceinline__ void ldsm4(uint32_t& r0, uint32_t& r1, uint32_t& r2, uint32_t& r3,
                                      uint32_t addr) {
    asm volatile("ldmatrix.sync.aligned.m8n8.x4.shared.b16 {%0,%1,%2,%3}, [%4];"
                 : "=r"(r0), "=r"(r1), "=r"(r2), "=r"(r3) : "r"(addr));
}
__device__ __forceinline__ void mma16816(float* c, const uint32_t* a, uint32_t b0, uint32_t b1) {
    asm volatile(
        "mma.sync.aligned.m16n8k16.row.col.f32.bf16.bf16.f32 "
        "{%0,%1,%2,%3}, {%4,%5,%6,%7}, {%8,%9}, {%0,%1,%2,%3};"
        : "+f"(c[0]), "+f"(c[1]), "+f"(c[2]), "+f"(c[3])
        : "r"(a[0]), "r"(a[1]), "r"(a[2]), "r"(a[3]), "r"(b0), "r"(b1));
}

// ---------------- fused prep + encode ----------------
// grid: [0,256)   codebook transpose (D,K)->(K,D) + bf16
//       [256,482) wdt flip / w2 (from cb directly) / key+ccnt init
//       [482,4578) encode: patch-embed GEMM + bias + relu
#define WEP 257
#define ENC_SMEM ((16 * 48 + 48 * WEP) * 4)   // 52416 B

__global__ __launch_bounds__(256) void k_prep_encode(const float* __restrict__ x,
                                                     const float* __restrict__ We,
                                                     const float* __restrict__ be,
                                                     const float* __restrict__ Wd,
                                                     const float* __restrict__ cb,
                                                     float* __restrict__ out_ze) {
    int bid = blockIdx.x;
    int tid = threadIdx.x;

    if (bid < 256) {   // codebook transpose
        __shared__ float t[32][33];
        int bx = bid & 15, by = bid >> 4;
        int tx = tid & 31, ty = tid >> 5;
        int xx = bx * 32 + tx;
        int y0 = by * 32;
        for (int r = ty; r < 32; r += 8)
            t[r][tx] = cb[(y0 + r) * NK + xx];
        __syncthreads();
        int xo = by * 32 + tx;
        int yo = bx * 32;
        for (int r = ty; r < 32; r += 8) {
            float v = t[tx][r];
            g_cbt[(yo + r) * ND + xo] = v;
            g_cbh[(yo + r) * ND + xo] = __float2bfloat16(v);
        }
        return;
    }
    if (bid < 482) {   // wdt / w2 / init
        int blk = bid - 256;
        if (blk < 96) {
            int e = blk * 256 + tid;
            int r = e >> 9, d = e & 511;
            int c = r >> 4, i = (r >> 2) & 3, j = r & 3;
            g_wdt[e] = Wd[(c * ND + d) * 16 + (3 - i) * 4 + (3 - j)];
        } else if (blk < 98) {
            int k = (blk - 96) * 256 + tid;
            float s = 0.f;
            for (int d = 0; d < ND; d++) {
                float v = cb[d * NK + k];   // coalesced across tid
                s += v * v;
            }
            g_w2[k] = s;
        } else {
            int m = (blk - 98) * 256 + tid;   // 128 blocks -> 32768
            g_key[m] = 0xFFFFFFFFFFFFFFFFull;
            g_ccnt[m] = 0;
        }
        return;
    }

    // ---- encode ----
    extern __shared__ float esm[];
    float* patch = esm;           // [16][48]
    float* wsm = esm + 16 * 48;   // [48][WEP]
    int e_blk = bid - 482;
    int blk = e_blk & 1023;
    int yy = e_blk >> 10;
    int b = blk >> 5, hl = blk & 31;
    int ph = yy & 1, dh = yy >> 1;

    for (int e = tid; e < 256 * 48; e += 256) {
        int r = e / 48, q = e - r * 48;
        wsm[q * WEP + r] = We[dh * (256 * 48) + e];
    }
    for (int e = tid; e < 768; e += 256) {
        int row = e >> 6, cc = e & 63;
        int c = row >> 2, i = row & 3;
        float v = x[((b * NC + c) * NH + (4 * hl + i)) * NH + ph * 64 + cc];
        patch[(cc >> 2) * 48 + c * 16 + i * 4 + (cc & 3)] = v;
    }
    __syncthreads();

    int d = dh * 256 + tid;
    float w[48];
#pragma unroll
    for (int q = 0; q < 48; q++) w[q] = wsm[q * WEP + tid];
    float bias = be[d];

    float acc[16];
    int mbase = b * NL + hl * 32 + ph * 16;
#pragma unroll
    for (int pos = 0; pos < 16; pos++) {
        float p0 = bias, p1 = 0.f, p2 = 0.f, p3 = 0.f;
        const float* pp = patch + pos * 48;
#pragma unroll
        for (int q = 0; q < 12; q++) {
            float* dst = (q & 3) == 0 ? &p0 : (q & 3) == 1 ? &p1 : (q & 3) == 2 ? &p2 : &p3;
            *dst += pp[4*q] * w[4*q] + pp[4*q+1] * w[4*q+1] + pp[4*q+2] * w[4*q+2] + pp[4*q+3] * w[4*q+3];
        }
        float v = fmaxf((p0 + p1) + (p2 + p3), 0.f);
        acc[pos] = v;
        __nv_bfloat16 h = __float2bfloat16(v);
        int zi = (mbase + pos) * ND + d;
        g_zh[zi] = h;
        g_zl[zi] = __float2bfloat16(v - __bfloat162float(h));
    }
    float4* o4 = reinterpret_cast<float4*>(out_ze + ((b * ND + d) * NHL + hl) * NHL + ph * 16);
#pragma unroll
    for (int q = 0; q < 4; q++)
        o4[q] = make_float4(acc[4*q], acc[4*q+1], acc[4*q+2], acc[4*q+3]);
}

// ---------------- pmat: P[k][r] = sum_d wdt[r][d] * cbt[k][d]  (512x48x512 GEMM) ----------------
// warp per k: cbt row cached in 16 regs/lane; wdt rows are L1-broadcast across warps.
__global__ __launch_bounds__(256) void k_pmat() {
    int lane = threadIdx.x & 31, wrp = threadIdx.x >> 5;
    int k = blockIdx.x * 8 + wrp;
    float creg[16];
#pragma unroll
    for (int t = 0; t < 16; t++) creg[t] = g_cbt[k * ND + t * 32 + lane];
#pragma unroll 1
    for (int r = 0; r < 48; r++) {
        float s = 0.f;
        const float* wr = g_wdt + r * ND + lane;
#pragma unroll
        for (int t = 0; t < 16; t++) s += creg[t] * wr[t * 32];
#pragma unroll
        for (int off = 16; off > 0; off >>= 1) s += __shfl_xor_sync(0xffffffffu, s, off);
        if (lane == 0) g_P[k * 48 + r] = s;
    }
}

// ---------------- pass 1: bf16 HMMA GEMM + approx argmin + candidate flagging ----------------
// Block tile 128x128; 128 threads = 4 warps in 2(m) x 2(n) grid; warp tile 64x64.
// 2-stage cp.async double-buffer; 2 blocks/SM (cross-block bubble overlap).
#define STG_BYTES 18432
#define NN_SMEM (4 * STG_BYTES)   // 73728 B

__device__ __forceinline__ void nn_fill(uint32_t smb, int stg, int kc, int m0, int n0, int tid) {
    uint32_t ab = smb + stg * STG_BYTES;
    uint32_t bb = smb + 2 * STG_BYTES + stg * STG_BYTES;
#pragma unroll
    for (int i = 0; i < 8; i++) {
        int u = i * 128 + tid;            // 0..1023
        int r = u >> 3, cg = u & 7;
        CP_ASYNC16(ab + r * 144 + cg * 16, g_zh + (m0 + r) * ND + kc * 64 + cg * 8);
    }
#pragma unroll
    for (int i = 0; i < 8; i++) {
        int u = i * 128 + tid;
        int r = u >> 3, cg = u & 7;
        CP_ASYNC16(bb + r * 144 + cg * 16, g_cbh + (n0 + r) * ND + kc * 64 + cg * 8);
    }
}

__global__ __launch_bounds__(128, 2) void k_nn() {
    extern __shared__ __align__(16) char nsm[];
    __shared__ float w2s[128];
    __shared__ unsigned rmin[128];
    int tid = threadIdx.x;
    int lane = tid & 31, wrp = tid >> 5;
    int wm = wrp & 1, wn = wrp >> 1;      // 2 x 2 warp grid; warp tile 64(m) x 64(n)
    int m0 = blockIdx.x * 128, n0 = blockIdx.y * 128;
    uint32_t smb = (uint32_t)__cvta_generic_to_shared(nsm);

    if (tid < 128) { w2s[tid] = g_w2[n0 + tid]; rmin[tid] = 0xFFFFFFFFu; }

    float cfr[4][8][4];
#pragma unroll
    for (int mt = 0; mt < 4; mt++)
#pragma unroll
        for (int nt = 0; nt < 8; nt++)
#pragma unroll
            for (int q = 0; q < 4; q++) cfr[mt][nt][q] = 0.f;

    nn_fill(smb, 0, 0, m0, n0, tid);
    CP_COMMIT();

    for (int kc = 0; kc < 8; kc++) {
        if (kc < 7) { nn_fill(smb, (kc + 1) & 1, kc + 1, m0, n0, tid); CP_COMMIT(); CP_WAIT(1); }
        else        { CP_WAIT(0); }
        __syncthreads();
        uint32_t sa = smb + (kc & 1) * STG_BYTES;
        uint32_t sb = smb + 2 * STG_BYTES + (kc & 1) * STG_BYTES;
#pragma unroll
        for (int ks = 0; ks < 4; ks++) {
            uint32_t afr[4][4];
#pragma unroll
            for (int mt = 0; mt < 4; mt++) {
                int r = wm * 64 + mt * 16 + ((lane >> 3) & 1) * 8 + (lane & 7);
                int cb = ks * 32 + (lane >> 4) * 16;
                ldsm4(afr[mt][0], afr[mt][1], afr[mt][2], afr[mt][3], sa + r * 144 + cb);
            }
            uint32_t bfr[8][2];
#pragma unroll
            for (int p = 0; p < 4; p++) {
                int r = wn * 64 + p * 16 + (lane >> 4) * 8 + (lane & 7);
                int cb = ks * 32 + ((lane >> 3) & 1) * 16;
                uint32_t b0, b1, b2, b3;
                ldsm4(b0, b1, b2, b3, sb + r * 144 + cb);
                bfr[2*p][0] = b0; bfr[2*p][1] = b1; bfr[2*p+1][0] = b2; bfr[2*p+1][1] = b3;
            }
#pragma unroll
            for (int mt = 0; mt < 4; mt++)
#pragma unroll
                for (int nt = 0; nt < 8; nt++)
                    mma16816(cfr[mt][nt], afr[mt], bfr[nt][0], bfr[nt][1]);
        }
        __syncthreads();
    }

    // epilogue phase 1: per-row block min (smem) + global packed atomicMin
#pragma unroll
    for (int mt = 0; mt < 4; mt++) {
#pragma unroll
        for (int h = 0; h < 2; h++) {
            int lr = wm * 64 + mt * 16 + (lane >> 2) + h * 8;
            unsigned long long best = 0xFFFFFFFFFFFFFFFFull;
#pragma unroll
            for (int nt = 0; nt < 8; nt++)
#pragma unroll
                for (int c2 = 0; c2 < 2; c2++) {
                    int kl = wn * 64 + nt * 8 + (lane & 3) * 2 + c2;
                    float dist = w2s[kl] - 2.f * cfr[mt][nt][h * 2 + c2];
                    unsigned long long key =
                        ((unsigned long long)mapf(dist) << 32) | (unsigned)(n0 + kl);
                    if (key < best) best = key;
                }
            unsigned long long o1 = __shfl_xor_sync(0xffffffffu, best, 1);
            if (o1 < best) best = o1;
            unsigned long long o2 = __shfl_xor_sync(0xffffffffu, best, 2);
            if (o2 < best) best = o2;
            if ((lane & 3) == 0) {
                atomicMin(&rmin[lr], (unsigned)(best >> 32));
                atomicMin(&g_key[m0 + lr], best);
            }
        }
    }
    __syncthreads();

    // epilogue phase 2: flag candidates (store packed key) within MARGIN of block row-min
#pragma unroll
    for (int mt = 0; mt < 4; mt++) {
#pragma unroll
        for (int h = 0; h < 2; h++) {
            int lr = wm * 64 + mt * 16 + (lane >> 2) + h * 8;
            float thr = unmapf(rmin[lr]) + MARGIN;
#pragma unroll
            for (int nt = 0; nt < 8; nt++)
#pragma unroll
                for (int c2 = 0; c2 < 2; c2++) {
                    int kl = wn * 64 + nt * 8 + (lane & 3) * 2 + c2;
                    float dist = w2s[kl] - 2.f * cfr[mt][nt][h * 2 + c2];
                    if (dist <= thr) {
                        int pos = atomicAdd(&g_ccnt[m0 + lr], 1);
                        if (pos < NSLOT)
                            g_cand[(m0 + lr) * NSLOT + pos] =
                                ((unsigned long long)mapf(dist) << 32) | (unsigned)(n0 + kl);
                    }
                }
        }
    }
}

// ---------------- pass 2: exact fp32 rescore (fast path: approx winner unambiguous) ----------------
__global__ __launch_bounds__(256) void k_rescore() {
    int tid = threadIdx.x, lane = tid & 31;
    int m = blockIdx.x * 8 + (tid >> 5);

    unsigned long long gkey = g_key[m];
    float amin = unmapf((unsigned)(gkey >> 32));
    int kstar = (int)(gkey & 0xFFFFFFFFu);
    int cnt = g_ccnt[m]; if (cnt > NSLOT) cnt = NSLOT;

    unsigned long long ck = 0xFFFFFFFFFFFFFFFFull;
    if (lane < cnt) ck = g_cand[m * NSLOT + lane];
    bool qual = (lane < cnt) && (ck != gkey) &&
                (unmapf((unsigned)(ck >> 32)) <= amin + MARGIN);
    unsigned bal = __ballot_sync(0xffffffffu, qual);
    if (bal == 0) {   // no challenger within global margin: approx winner is exact
        if (lane == 0) g_idx[m] = kstar;
        return;
    }

    // slow path: reconstruct z (fp32 from hi+lo) and exactly rescore kstar + challengers
    float4 z[4];
#pragma unroll
    for (int t = 0; t < 4; t++) {
        int d = t * 128 + lane * 4;
        uint2 hh = *reinterpret_cast<const uint2*>(g_zh + m * ND + d);
        uint2 ll = *reinterpret_cast<const uint2*>(g_zl + m * ND + d);
        __nv_bfloat162 h0 = *reinterpret_cast<__nv_bfloat162*>(&hh.x);
        __nv_bfloat162 h1 = *reinterpret_cast<__nv_bfloat162*>(&hh.y);
        __nv_bfloat162 l0 = *reinterpret_cast<__nv_bfloat162*>(&ll.x);
        __nv_bfloat162 l1 = *reinterpret_cast<__nv_bfloat162*>(&ll.y);
        z[t].x = __bfloat162float(h0.x) + __bfloat162float(l0.x);
        z[t].y = __bfloat162float(h0.y) + __bfloat162float(l0.y);
        z[t].z = __bfloat162float(h1.x) + __bfloat162float(l1.x);
        z[t].w = __bfloat162float(h1.y) + __bfloat162float(l1.y);
    }
    unsigned mycand = (unsigned)(ck & 0xFFFFFFFFu);
    unsigned long long best = 0xFFFFFFFFFFFFFFFFull;
    int k = kstar;
    unsigned rem = bal;
    for (;;) {
        float s = 0.f;
#pragma unroll
        for (int t = 0; t < 4; t++) {
            float4 cv = *reinterpret_cast<const float4*>(g_cbt + k * ND + t * 128 + lane * 4);
            s += z[t].x * cv.x + z[t].y * cv.y + z[t].z * cv.z + z[t].w * cv.w;
        }
#pragma unroll
        for (int off = 16; off > 0; off >>= 1) s += __shfl_xor_sync(0xffffffffu, s, off);
        float dist = g_w2[k] - 2.f * s;
        unsigned long long key = ((unsigned long long)mapf(dist) << 32) | (unsigned)k;
        if (key < best) best = key;
        if (!rem) break;
        int src = __ffs(rem) - 1;
        rem &= rem - 1;
        k = (int)__shfl_sync(0xffffffffu, mycand, src);
    }
    if (lane == 0) g_idx[m] = (int)(best & 0xFFFFFFFFu);
}

// ---------------- gather (emb) + decode-via-P (recon) ----------------
// Decode is a pure gather now: recon = sigmoid(P[k[pos]][r] + bd[c]).
#define ZQP 517
#define GDE_SMEM (32 * ZQP * 4)   // 66176 B -> 3 blocks/SM
__global__ __launch_bounds__(512) void k_gde(const float* __restrict__ bd,
                                             float* __restrict__ out_emb,
                                             float* __restrict__ out_recon) {
    extern __shared__ float smf[];
    float* zq = smf;               // [32][ZQP]
    __shared__ int karr[32];

    int blk = blockIdx.x;
    int b = blk >> 5, hl = blk & 31;
    int tid = threadIdx.x;

    if (tid < 32) karr[tid] = g_idx[b * NL + hl * 32 + tid];
    __syncthreads();

    // gather codebook rows (coalesced reads, d fast)
    for (int e = tid; e < 32 * ND; e += 512) {
        int wl = e >> 9, d = e & 511;
        zq[wl * ZQP + d] = g_cbt[karr[wl] * ND + d];
    }
    __syncthreads();

    // emb output (B,D,L): transposed read from smem, coalesced 128B writes
    float* eb = out_emb + b * (ND * NL) + hl * 32;
    for (int e = tid; e < 16384; e += 512) {
        int d = e >> 5, wl = e & 31;
        eb[d * NL + wl] = zq[wl * ZQP + d];
    }

    // recon: gather P rows + bias + sigmoid (1536 outputs)
#pragma unroll
    for (int it = 0; it < 3; it++) {
        int o = it * 512 + tid;
        int wlo = o / 48;
        int ro = o - wlo * 48;
        float v = g_P[karr[wlo] * 48 + ro];
        int cc = ro >> 4, ii = (ro >> 2) & 3, jj = ro & 3;
        v += bd[cc];
        float s = 1.f / (1.f + __expf(-v));
        out_recon[((b * NC + cc) * NH + (4 * hl + ii)) * NH + wlo * 4 + jj] = s;
    }
}

// ---------------- launch ----------------
extern "C" void kernel_launch(void* const* d_in, const int* in_sizes, int n_in,
                              void* d_out, int out_size) {
    const float* x  = (const float*)d_in[0];
    const float* We = (const float*)d_in[1];
    const float* be = (const float*)d_in[2];
    const float* Wd = (const float*)d_in[3];
    const float* bd = (const float*)d_in[4];
    const float* cb = (const float*)d_in[5];

    float* out = (float*)d_out;
    float* out_recon = out;
    float* out_ze    = out + RECON_N;
    float* out_emb   = out + RECON_N + ZE_N;

    cudaFuncSetAttribute(k_prep_encode, cudaFuncAttributeMaxDynamicSharedMemorySize, ENC_SMEM);
    cudaFuncSetAttribute(k_nn, cudaFuncAttributeMaxDynamicSharedMemorySize, NN_SMEM);
    cudaFuncSetAttribute(k_gde, cudaFuncAttributeMaxDynamicSharedMemorySize, GDE_SMEM);

    k_prep_encode<<<4578, 256, ENC_SMEM>>>(x, We, be, Wd, cb, out_ze);
    k_pmat<<<64, 256>>>();
    k_nn<<<dim3(256, 4), 128, NN_SMEM>>>();
    k_rescore<<<4096, 256>>>();
    k_gde<<<1024, 512, GDE_SMEM>>>(bd, out_emb, out_recon);
}

// round 16
// speedup vs baseline: 1.5573x; 1.2833x over previous
#include <cuda_runtime.h>
#include <cuda_bf16.h>
#include <cstdint>

// VQ-VAE forward on GB300 (base sm_103 target: mma.sync/ldmatrix/cp.async).
// Outputs (flattened, in order): recon (32,3,128,128), z_e (32,512,32,32), emb (32,512,32,32)

#define NB 32
#define NC 3
#define NH 128
#define ND 512
#define NK 512
#define NHL 32
#define NL 1024
#define NM (NB * NL)  // 32768

#define RECON_N (32 * 3 * 128 * 128)
#define ZE_N (32 * 512 * 32 * 32)
#define MARGIN 0.45f
#define NSLOT 16
#define XP 152   // split-matrix pitch (elements): 144 used + 8 pad = 19 x 16B rows

// ---------------- scratch (static device memory; no allocations) ----------------
__device__ __nv_bfloat16 g_zh[NM * ND];   // z_e hi split, row-major (M, D)
__device__ __nv_bfloat16 g_zl[NM * ND];   // z_e lo split
__device__ __nv_bfloat16 g_cbh[NK * ND];  // codebook^T bf16 (K, D)
__device__ __nv_bfloat16 g_xsplit[NM * XP];   // patch matrix: [xh(48) | xl(48) | xh(48)]
__device__ __nv_bfloat16 g_wsplit[ND * XP];   // We matrix:    [wh(48) | wh(48) | wl(48)]
__device__ float g_cbt[NK * ND];          // codebook^T fp32 (K, D)
__device__ float g_w2[NK];                // ||W[:,k]||^2 (fp32 exact)
__device__ float g_wdt[48 * ND];          // decoder weights, spatial flip baked in
__device__ float g_P[NK * 48];            // precomputed decode: P[k][r] = wdt[r].cbt[k]
__device__ int   g_idx[NM];               // final argmin indices
__device__ unsigned long long g_key[NM];  // pass-1 packed (approx dist, k)
__device__ int g_ccnt[NM];                // candidate counts
__device__ unsigned long long g_cand[NM * NSLOT];  // candidate packed (dist, k)

// ---------------- small helpers ----------------
__device__ __forceinline__ unsigned mapf(float x) {
    unsigned u = __float_as_uint(x);
    return (u & 0x80000000u) ? ~u : (u | 0x80000000u);   // order-preserving
}
__device__ __forceinline__ float unmapf(unsigned m) {
    unsigned u = (m & 0x80000000u) ? (m ^ 0x80000000u) : ~m;
    return __uint_as_float(u);
}

#define CP_ASYNC16(smaddr, gptr) \
    asm volatile("cp.async.cg.shared.global [%0], [%1], 16;" :: "r"(smaddr), "l"(gptr))
#define CP_COMMIT() asm volatile("cp.async.commit_group;" ::: "memory")
#define CP_WAIT(n)  asm volatile("cp.async.wait_group %0;" :: "n"(n) : "memory")

__device__ __forceinline__ void ldsm4(uint32_t& r0, uint32_t& r1, uint32_t& r2, uint32_t& r3,
                                      uint32_t addr) {
    asm volatile("ldmatrix.sync.aligned.m8n8.x4.shared.b16 {%0,%1,%2,%3}, [%4];"
                 : "=r"(r0), "=r"(r1), "=r"(r2), "=r"(r3) : "r"(addr));
}
__device__ __forceinline__ void mma16816(float* c, const uint32_t* a, uint32_t b0, uint32_t b1) {
    asm volatile(
        "mma.sync.aligned.m16n8k16.row.col.f32.bf16.bf16.f32 "
        "{%0,%1,%2,%3}, {%4,%5,%6,%7}, {%8,%9}, {%0,%1,%2,%3};"
        : "+f"(c[0]), "+f"(c[1]), "+f"(c[2]), "+f"(c[3])
        : "r"(a[0]), "r"(a[1]), "r"(a[2]), "r"(a[3]), "r"(b0), "r"(b1));
}

// ---------------- fused prep (range-partitioned, 1602 blocks x 256) ----------------
// [0,256)    codebook transpose (D,K)->(K,D) fp32 + bf16
// [256,352)  wdt spatial flip
// [352,354)  w2 from cb
// [354,482)  key/ccnt init
// [482,578)  We split matrix [wh|wh|wl]
// [578,1602) x patch split matrix [xh|xl|xh]
__global__ __launch_bounds__(256) void k_prep(const float* __restrict__ x,
                                              const float* __restrict__ We,
                                              const float* __restrict__ Wd,
                                              const float* __restrict__ cb) {
    int bid = blockIdx.x;
    int tid = threadIdx.x;

    if (bid < 256) {   // codebook transpose
        __shared__ float t[32][33];
        int bx = bid & 15, by = bid >> 4;
        int tx = tid & 31, ty = tid >> 5;
        int xx = bx * 32 + tx;
        int y0 = by * 32;
        for (int r = ty; r < 32; r += 8)
            t[r][tx] = cb[(y0 + r) * NK + xx];
        __syncthreads();
        int xo = by * 32 + tx;
        int yo = bx * 32;
        for (int r = ty; r < 32; r += 8) {
            float v = t[tx][r];
            g_cbt[(yo + r) * ND + xo] = v;
            g_cbh[(yo + r) * ND + xo] = __float2bfloat16(v);
        }
        return;
    }
    if (bid < 578) {
        int blk = bid - 256;
        if (blk < 96) {              // wdt flip
            int e = blk * 256 + tid;
            int r = e >> 9, d = e & 511;
            int c = r >> 4, i = (r >> 2) & 3, j = r & 3;
            g_wdt[e] = Wd[(c * ND + d) * 16 + (3 - i) * 4 + (3 - j)];
        } else if (blk < 98) {       // w2
            int k = (blk - 96) * 256 + tid;
            float s = 0.f;
            for (int d = 0; d < ND; d++) {
                float v = cb[d * NK + k];
                s += v * v;
            }
            g_w2[k] = s;
        } else if (blk < 226) {      // init
            int m = (blk - 98) * 256 + tid;
            g_key[m] = 0xFFFFFFFFFFFFFFFFull;
            g_ccnt[m] = 0;
        } else {                     // We split: blk in [226,322)
            int e = (blk - 226) * 256 + tid;   // < 24576
            int d = e / 48, q = e - d * 48;
            float v = We[e];
            __nv_bfloat16 wh = __float2bfloat16(v);
            __nv_bfloat16 wl = __float2bfloat16(v - __bfloat162float(wh));
            g_wsplit[d * XP + q] = wh;
            g_wsplit[d * XP + 48 + q] = wh;
            g_wsplit[d * XP + 96 + q] = wl;
        }
        return;
    }

    // x patch split: block per (b, hl)
    int e_blk = bid - 578;         // [0, 1024)
    int b = e_blk >> 5, hl = e_blk & 31;
#pragma unroll
    for (int i = 0; i < 6; i++) {
        int e = i * 256 + tid;     // < 1536
        int row = e >> 7;          // c*4 + ii
        int col = e & 127;
        int c = row >> 2, ii = row & 3;
        float v = x[((b * NC + c) * NH + (4 * hl + ii)) * NH + col];
        int wl = col >> 2, j = col & 3;
        int q = c * 16 + ii * 4 + j;
        int base = (b * NL + hl * 32 + wl) * XP + q;
        __nv_bfloat16 xh = __float2bfloat16(v);
        __nv_bfloat16 xl = __float2bfloat16(v - __bfloat162float(xh));
        g_xsplit[base] = xh;
        g_xsplit[base + 48] = xl;
        g_xsplit[base + 96] = xh;
    }
}

// ---------------- encode GEMM: z[m][n] = xsplit[m] . wsplit[n]  (K=144, bf16 HMMA) ----------------
// Block 128m x 128n, 128 threads, warp tile 64x64 (2x2), single K pass (9 ks), 2 blocks/SM.
// Epilogue: z tile staged in reused smem (pitch 129), bias+relu, coalesced outputs.
#define EPITCH 304                     // A/B smem row pitch bytes (19 x 16B)
#define EST (128 * EPITCH)             // 38912 B per operand
#define EMM_SMEM (2 * EST)             // 77824 B

__global__ __launch_bounds__(128, 2) void k_encode_mma(const float* __restrict__ be,
                                                       float* __restrict__ out_ze) {
    extern __shared__ __align__(16) char esm2[];
    __shared__ float bsm[128];
    int tid = threadIdx.x;
    int lane = tid & 31, wrp = tid >> 5;
    int wm = wrp & 1, wn = wrp >> 1;
    int m0 = blockIdx.x * 128, n0 = blockIdx.y * 128;
    uint32_t smb = (uint32_t)__cvta_generic_to_shared(esm2);

    // fill A (xsplit rows m0..m0+127) and B (wsplit rows n0..n0+127): 19 chunks/row
#pragma unroll
    for (int i = 0; i < 19; i++) {
        int c = i * 128 + tid;         // [0, 2432)
        int r = c / 19, ch = c - r * 19;
        CP_ASYNC16(smb + r * EPITCH + ch * 16, g_xsplit + (m0 + r) * XP + ch * 8);
    }
#pragma unroll
    for (int i = 0; i < 19; i++) {
        int c = i * 128 + tid;
        int r = c / 19, ch = c - r * 19;
        CP_ASYNC16(smb + EST + r * EPITCH + ch * 16, g_wsplit + (n0 + r) * XP + ch * 8);
    }
    CP_COMMIT();
    if (tid < 128) bsm[tid] = be[n0 + tid];

    float cfr[4][8][4];
#pragma unroll
    for (int mt = 0; mt < 4; mt++)
#pragma unroll
        for (int nt = 0; nt < 8; nt++)
#pragma unroll
            for (int q = 0; q < 4; q++) cfr[mt][nt][q] = 0.f;

    CP_WAIT(0);
    __syncthreads();

#pragma unroll
    for (int ks = 0; ks < 9; ks++) {
        uint32_t afr[4][4];
#pragma unroll
        for (int mt = 0; mt < 4; mt++) {
            int r = wm * 64 + mt * 16 + ((lane >> 3) & 1) * 8 + (lane & 7);
            int cb2 = ks * 32 + (lane >> 4) * 16;
            ldsm4(afr[mt][0], afr[mt][1], afr[mt][2], afr[mt][3], smb + r * EPITCH + cb2);
        }
        uint32_t bfr[8][2];
#pragma unroll
        for (int p = 0; p < 4; p++) {
            int r = wn * 64 + p * 16 + (lane >> 4) * 8 + (lane & 7);
            int cb2 = ks * 32 + ((lane >> 3) & 1) * 16;
            uint32_t b0, b1, b2, b3;
            ldsm4(b0, b1, b2, b3, smb + EST + r * EPITCH + cb2);
            bfr[2*p][0] = b0; bfr[2*p][1] = b1; bfr[2*p+1][0] = b2; bfr[2*p+1][1] = b3;
        }
#pragma unroll
        for (int mt = 0; mt < 4; mt++)
#pragma unroll
            for (int nt = 0; nt < 8; nt++)
                mma16816(cfr[mt][nt], afr[mt], bfr[nt][0], bfr[nt][1]);
    }
    __syncthreads();   // all ldmatrix reads done; safe to reuse smem

    // stage z tile (bias + relu) into smem, pitch 129 floats
    float* zt = reinterpret_cast<float*>(esm2);
#pragma unroll
    for (int mt = 0; mt < 4; mt++)
#pragma unroll
        for (int nt = 0; nt < 8; nt++)
#pragma unroll
            for (int h = 0; h < 2; h++)
#pragma unroll
                for (int c2 = 0; c2 < 2; c2++) {
                    int lr = wm * 64 + mt * 16 + (lane >> 2) + h * 8;
                    int nl = wn * 64 + nt * 8 + (lane & 3) * 2 + c2;
                    float v = fmaxf(cfr[mt][nt][h * 2 + c2] + bsm[nl], 0.f);
                    zt[lr * 129 + nl] = v;
                }
    __syncthreads();

    // outputs
    int b = m0 >> 10;
    int hl_base = (m0 & 1023) >> 5;    // 4 consecutive hl values

    // g_zh / g_zl: rows (m0+i), cols n0+tid (lanes contiguous)
#pragma unroll 4
    for (int i = 0; i < 128; i++) {
        float v = zt[i * 129 + tid];
        __nv_bfloat16 h = __float2bfloat16(v);
        int gi = (m0 + i) * ND + n0 + tid;
        g_zh[gi] = h;
        g_zl[gi] = __float2bfloat16(v - __bfloat162float(h));
    }

    // out_ze (B,D,HL,WL): warp per (d, hl) row, lanes = wl (128B coalesced)
    for (int ro = wrp; ro < 512; ro += 4) {
        int dl = ro >> 2, hl_l = ro & 3;
        float v = zt[(hl_l * 32 + lane) * 129 + dl];
        out_ze[((b * ND + n0 + dl) * NHL + hl_base + hl_l) * NHL + lane] = v;
    }
}

// ---------------- pmat: P[k][r] = sum_d wdt[r][d] * cbt[k][d] ----------------
__global__ __launch_bounds__(256) void k_pmat() {
    int lane = threadIdx.x & 31, wrp = threadIdx.x >> 5;
    int k = blockIdx.x * 8 + wrp;
    float creg[16];
#pragma unroll
    for (int t = 0; t < 16; t++) creg[t] = g_cbt[k * ND + t * 32 + lane];
#pragma unroll 1
    for (int r = 0; r < 48; r++) {
        float s = 0.f;
        const float* wr = g_wdt + r * ND + lane;
#pragma unroll
        for (int t = 0; t < 16; t++) s += creg[t] * wr[t * 32];
#pragma unroll
        for (int off = 16; off > 0; off >>= 1) s += __shfl_xor_sync(0xffffffffu, s, off);
        if (lane == 0) g_P[k * 48 + r] = s;
    }
}

// ---------------- pass 1: bf16 HMMA GEMM + approx argmin + candidate flagging ----------------
#define STG_BYTES 18432
#define NN_SMEM (4 * STG_BYTES)

__device__ __forceinline__ void nn_fill(uint32_t smb, int stg, int kc, int m0, int n0, int tid) {
    uint32_t ab = smb + stg * STG_BYTES;
    uint32_t bb = smb + 2 * STG_BYTES + stg * STG_BYTES;
#pragma unroll
    for (int i = 0; i < 8; i++) {
        int u = i * 128 + tid;
        int r = u >> 3, cg = u & 7;
        CP_ASYNC16(ab + r * 144 + cg * 16, g_zh + (m0 + r) * ND + kc * 64 + cg * 8);
    }
#pragma unroll
    for (int i = 0; i < 8; i++) {
        int u = i * 128 + tid;
        int r = u >> 3, cg = u & 7;
        CP_ASYNC16(bb + r * 144 + cg * 16, g_cbh + (n0 + r) * ND + kc * 64 + cg * 8);
    }
}

__global__ __launch_bounds__(128, 2) void k_nn() {
    extern __shared__ __align__(16) char nsm[];
    __shared__ float w2s[128];
    __shared__ unsigned rmin[128];
    int tid = threadIdx.x;
    int lane = tid & 31, wrp = tid >> 5;
    int wm = wrp & 1, wn = wrp >> 1;
    int m0 = blockIdx.x * 128, n0 = blockIdx.y * 128;
    uint32_t smb = (uint32_t)__cvta_generic_to_shared(nsm);

    if (tid < 128) { w2s[tid] = g_w2[n0 + tid]; rmin[tid] = 0xFFFFFFFFu; }

    float cfr[4][8][4];
#pragma unroll
    for (int mt = 0; mt < 4; mt++)
#pragma unroll
        for (int nt = 0; nt < 8; nt++)
#pragma unroll
            for (int q = 0; q < 4; q++) cfr[mt][nt][q] = 0.f;

    nn_fill(smb, 0, 0, m0, n0, tid);
    CP_COMMIT();

    for (int kc = 0; kc < 8; kc++) {
        if (kc < 7) { nn_fill(smb, (kc + 1) & 1, kc + 1, m0, n0, tid); CP_COMMIT(); CP_WAIT(1); }
        else        { CP_WAIT(0); }
        __syncthreads();
        uint32_t sa = smb + (kc & 1) * STG_BYTES;
        uint32_t sb = smb + 2 * STG_BYTES + (kc & 1) * STG_BYTES;
#pragma unroll
        for (int ks = 0; ks < 4; ks++) {
            uint32_t afr[4][4];
#pragma unroll
            for (int mt = 0; mt < 4; mt++) {
                int r = wm * 64 + mt * 16 + ((lane >> 3) & 1) * 8 + (lane & 7);
                int cb2 = ks * 32 + (lane >> 4) * 16;
                ldsm4(afr[mt][0], afr[mt][1], afr[mt][2], afr[mt][3], sa + r * 144 + cb2);
            }
            uint32_t bfr[8][2];
#pragma unroll
            for (int p = 0; p < 4; p++) {
                int r = wn * 64 + p * 16 + (lane >> 4) * 8 + (lane & 7);
                int cb2 = ks * 32 + ((lane >> 3) & 1) * 16;
                uint32_t b0, b1, b2, b3;
                ldsm4(b0, b1, b2, b3, sb + r * 144 + cb2);
                bfr[2*p][0] = b0; bfr[2*p][1] = b1; bfr[2*p+1][0] = b2; bfr[2*p+1][1] = b3;
            }
#pragma unroll
            for (int mt = 0; mt < 4; mt++)
#pragma unroll
                for (int nt = 0; nt < 8; nt++)
                    mma16816(cfr[mt][nt], afr[mt], bfr[nt][0], bfr[nt][1]);
        }
        __syncthreads();
    }

    // epilogue phase 1: per-row block min (smem) + global packed atomicMin
#pragma unroll
    for (int mt = 0; mt < 4; mt++) {
#pragma unroll
        for (int h = 0; h < 2; h++) {
            int lr = wm * 64 + mt * 16 + (lane >> 2) + h * 8;
            unsigned long long best = 0xFFFFFFFFFFFFFFFFull;
#pragma unroll
            for (int nt = 0; nt < 8; nt++)
#pragma unroll
                for (int c2 = 0; c2 < 2; c2++) {
                    int kl = wn * 64 + nt * 8 + (lane & 3) * 2 + c2;
                    float dist = w2s[kl] - 2.f * cfr[mt][nt][h * 2 + c2];
                    unsigned long long key =
                        ((unsigned long long)mapf(dist) << 32) | (unsigned)(n0 + kl);
                    if (key < best) best = key;
                }
            unsigned long long o1 = __shfl_xor_sync(0xffffffffu, best, 1);
            if (o1 < best) best = o1;
            unsigned long long o2 = __shfl_xor_sync(0xffffffffu, best, 2);
            if (o2 < best) best = o2;
            if ((lane & 3) == 0) {
                atomicMin(&rmin[lr], (unsigned)(best >> 32));
                atomicMin(&g_key[m0 + lr], best);
            }
        }
    }
    __syncthreads();

    // epilogue phase 2: flag candidates within MARGIN of block row-min
#pragma unroll
    for (int mt = 0; mt < 4; mt++) {
#pragma unroll
        for (int h = 0; h < 2; h++) {
            int lr = wm * 64 + mt * 16 + (lane >> 2) + h * 8;
            float thr = unmapf(rmin[lr]) + MARGIN;
#pragma unroll
            for (int nt = 0; nt < 8; nt++)
#pragma unroll
                for (int c2 = 0; c2 < 2; c2++) {
                    int kl = wn * 64 + nt * 8 + (lane & 3) * 2 + c2;
                    float dist = w2s[kl] - 2.f * cfr[mt][nt][h * 2 + c2];
                    if (dist <= thr) {
                        int pos = atomicAdd(&g_ccnt[m0 + lr], 1);
                        if (pos < NSLOT)
                            g_cand[(m0 + lr) * NSLOT + pos] =
                                ((unsigned long long)mapf(dist) << 32) | (unsigned)(n0 + kl);
                    }
                }
        }
    }
}

// ---------------- pass 2: exact fp32 rescore (fast path: approx winner unambiguous) ----------------
__global__ __launch_bounds__(256) void k_rescore() {
    int tid = threadIdx.x, lane = tid & 31;
    int m = blockIdx.x * 8 + (tid >> 5);

    unsigned long long gkey = g_key[m];
    float amin = unmapf((unsigned)(gkey >> 32));
    int kstar = (int)(gkey & 0xFFFFFFFFu);
    int cnt = g_ccnt[m]; if (cnt > NSLOT) cnt = NSLOT;

    unsigned long long ck = 0xFFFFFFFFFFFFFFFFull;
    if (lane < cnt) ck = g_cand[m * NSLOT + lane];
    bool qual = (lane < cnt) && (ck != gkey) &&
                (unmapf((unsigned)(ck >> 32)) <= amin + MARGIN);
    unsigned bal = __ballot_sync(0xffffffffu, qual);
    if (bal == 0) {
        if (lane == 0) g_idx[m] = kstar;
        return;
    }

    float4 z[4];
#pragma unroll
    for (int t = 0; t < 4; t++) {
        int d = t * 128 + lane * 4;
        uint2 hh = *reinterpret_cast<const uint2*>(g_zh + m * ND + d);
        uint2 ll = *reinterpret_cast<const uint2*>(g_zl + m * ND + d);
        __nv_bfloat162 h0 = *reinterpret_cast<__nv_bfloat162*>(&hh.x);
        __nv_bfloat162 h1 = *reinterpret_cast<__nv_bfloat162*>(&hh.y);
        __nv_bfloat162 l0 = *reinterpret_cast<__nv_bfloat162*>(&ll.x);
        __nv_bfloat162 l1 = *reinterpret_cast<__nv_bfloat162*>(&ll.y);
        z[t].x = __bfloat162float(h0.x) + __bfloat162float(l0.x);
        z[t].y = __bfloat162float(h0.y) + __bfloat162float(l0.y);
        z[t].z = __bfloat162float(h1.x) + __bfloat162float(l1.x);
        z[t].w = __bfloat162float(h1.y) + __bfloat162float(l1.y);
    }
    unsigned mycand = (unsigned)(ck & 0xFFFFFFFFu);
    unsigned long long best = 0xFFFFFFFFFFFFFFFFull;
    int k = kstar;
    unsigned rem = bal;
    for (;;) {
        float s = 0.f;
#pragma unroll
        for (int t = 0; t < 4; t++) {
            float4 cv = *reinterpret_cast<const float4*>(g_cbt + k * ND + t * 128 + lane * 4);
            s += z[t].x * cv.x + z[t].y * cv.y + z[t].z * cv.z + z[t].w * cv.w;
        }
#pragma unroll
        for (int off = 16; off > 0; off >>= 1) s += __shfl_xor_sync(0xffffffffu, s, off);
        float dist = g_w2[k] - 2.f * s;
        unsigned long long key = ((unsigned long long)mapf(dist) << 32) | (unsigned)k;
        if (key < best) best = key;
        if (!rem) break;
        int src = __ffs(rem) - 1;
        rem &= rem - 1;
        k = (int)__shfl_sync(0xffffffffu, mycand, src);
    }
    if (lane == 0) g_idx[m] = (int)(best & 0xFFFFFFFFu);
}

// ---------------- gather (emb) + decode-via-P (recon) ----------------
#define ZQP 517
#define GDE_SMEM (32 * ZQP * 4)   // 66176 B -> 3 blocks/SM
__global__ __launch_bounds__(512) void k_gde(const float* __restrict__ bd,
                                             float* __restrict__ out_emb,
                                             float* __restrict__ out_recon) {
    extern __shared__ float smf[];
    float* zq = smf;               // [32][ZQP]
    __shared__ int karr[32];

    int blk = blockIdx.x;
    int b = blk >> 5, hl = blk & 31;
    int tid = threadIdx.x;

    if (tid < 32) karr[tid] = g_idx[b * NL + hl * 32 + tid];
    __syncthreads();

    for (int e = tid; e < 32 * ND; e += 512) {
        int wl = e >> 9, d = e & 511;
        zq[wl * ZQP + d] = g_cbt[karr[wl] * ND + d];
    }
    __syncthreads();

    float* eb = out_emb + b * (ND * NL) + hl * 32;
    for (int e = tid; e < 16384; e += 512) {
        int d = e >> 5, wl = e & 31;
        eb[d * NL + wl] = zq[wl * ZQP + d];
    }

#pragma unroll
    for (int it = 0; it < 3; it++) {
        int o = it * 512 + tid;
        int wlo = o / 48;
        int ro = o - wlo * 48;
        float v = g_P[karr[wlo] * 48 + ro];
        int cc = ro >> 4, ii = (ro >> 2) & 3, jj = ro & 3;
        v += bd[cc];
        float s = 1.f / (1.f + __expf(-v));
        out_recon[((b * NC + cc) * NH + (4 * hl + ii)) * NH + wlo * 4 + jj] = s;
    }
}

// ---------------- launch ----------------
extern "C" void kernel_launch(void* const* d_in, const int* in_sizes, int n_in,
                              void* d_out, int out_size) {
    const float* x  = (const float*)d_in[0];
    const float* We = (const float*)d_in[1];
    const float* be = (const float*)d_in[2];
    const float* Wd = (const float*)d_in[3];
    const float* bd = (const float*)d_in[4];
    const float* cb = (const float*)d_in[5];

    float* out = (float*)d_out;
    float* out_recon = out;
    float* out_ze    = out + RECON_N;
    float* out_emb   = out + RECON_N + ZE_N;

    cudaFuncSetAttribute(k_encode_mma, cudaFuncAttributeMaxDynamicSharedMemorySize, EMM_SMEM);
    cudaFuncSetAttribute(k_nn, cudaFuncAttributeMaxDynamicSharedMemorySize, NN_SMEM);
    cudaFuncSetAttribute(k_gde, cudaFuncAttributeMaxDynamicSharedMemorySize, GDE_SMEM);

    k_prep<<<1602, 256>>>(x, We, Wd, cb);
    k_encode_mma<<<dim3(256, 4), 128, EMM_SMEM>>>(be, out_ze);
    k_pmat<<<64, 256>>>();
    k_nn<<<dim3(256, 4), 128, NN_SMEM>>>();
    k_rescore<<<4096, 256>>>();
    k_gde<<<1024, 512, GDE_SMEM>>>(bd, out_emb, out_recon);
}

// round 17
// speedup vs baseline: 1.7040x; 1.0942x over previous
#include <cuda_runtime.h>
#include <cuda_bf16.h>
#include <cstdint>

// VQ-VAE forward on GB300 (base sm_103 target: mma.sync/ldmatrix/cp.async).
// Outputs (flattened, in order): recon (32,3,128,128), z_e (32,512,32,32), emb (32,512,32,32)

#define NB 32
#define NC 3
#define NH 128
#define ND 512
#define NK 512
#define NHL 32
#define NL 1024
#define NM (NB * NL)  // 32768

#define RECON_N (32 * 3 * 128 * 128)
#define ZE_N (32 * 512 * 32 * 32)
#define MARGIN 0.45f
#define NSLOT 16
#define XP 152   // split-matrix pitch (elements): 144 used + 8 pad = 19 x 16B rows

// ---------------- scratch (static device memory; no allocations) ----------------
__device__ __nv_bfloat16 g_zh[NM * ND];   // z_e hi split, row-major (M, D)
__device__ __nv_bfloat16 g_zl[NM * ND];   // z_e lo split
__device__ __nv_bfloat16 g_cbh[NK * ND];  // codebook^T bf16 (K, D)
__device__ __nv_bfloat16 g_xsplit[NM * XP];   // patch matrix: [xh(48) | xl(48) | xh(48)]
__device__ __nv_bfloat16 g_wsplit[ND * XP];   // We matrix:    [wh(48) | wh(48) | wl(48)]
__device__ float g_cbt[NK * ND];          // codebook^T fp32 (K, D)
__device__ float g_w2[NK];                // ||W[:,k]||^2 (fp32 exact)
__device__ float g_wdt[48 * ND];          // decoder weights, spatial flip baked in
__device__ float g_P[NK * 48];            // precomputed decode: P[k][r] = wdt[r].cbt[k]
__device__ int   g_idx[NM];               // final argmin indices
__device__ unsigned long long g_key[NM];  // pass-1 packed (approx dist, k)
__device__ int g_ccnt[NM];                // candidate counts
__device__ unsigned long long g_cand[NM * NSLOT];  // candidate packed (dist, k)

// ---------------- small helpers ----------------
__device__ __forceinline__ unsigned mapf(float x) {
    unsigned u = __float_as_uint(x);
    return (u & 0x80000000u) ? ~u : (u | 0x80000000u);   // order-preserving
}
__device__ __forceinline__ float unmapf(unsigned m) {
    unsigned u = (m & 0x80000000u) ? (m ^ 0x80000000u) : ~m;
    return __uint_as_float(u);
}

#define CP_ASYNC16(smaddr, gptr) \
    asm volatile("cp.async.cg.shared.global [%0], [%1], 16;" :: "r"(smaddr), "l"(gptr))
#define CP_COMMIT() asm volatile("cp.async.commit_group;" ::: "memory")
#define CP_WAIT(n)  asm volatile("cp.async.wait_group %0;" :: "n"(n) : "memory")

__device__ __forceinline__ void ldsm4(uint32_t& r0, uint32_t& r1, uint32_t& r2, uint32_t& r3,
                                      uint32_t addr) {
    asm volatile("ldmatrix.sync.aligned.m8n8.x4.shared.b16 {%0,%1,%2,%3}, [%4];"
                 : "=r"(r0), "=r"(r1), "=r"(r2), "=r"(r3) : "r"(addr));
}
__device__ __forceinline__ void mma16816(float* c, const uint32_t* a, uint32_t b0, uint32_t b1) {
    asm volatile(
        "mma.sync.aligned.m16n8k16.row.col.f32.bf16.bf16.f32 "
        "{%0,%1,%2,%3}, {%4,%5,%6,%7}, {%8,%9}, {%0,%1,%2,%3};"
        : "+f"(c[0]), "+f"(c[1]), "+f"(c[2]), "+f"(c[3])
        : "r"(a[0]), "r"(a[1]), "r"(a[2]), "r"(a[3]), "r"(b0), "r"(b1));
}

// ---------------- fused prep (range-partitioned, 1602 blocks x 256) ----------------
// [0,256)    codebook transpose (D,K)->(K,D) fp32 + bf16
// [256,352)  wdt spatial flip
// [352,354)  w2 from cb
// [354,482)  key/ccnt init
// [482,578)  We split matrix [wh|wh|wl]
// [578,1602) x patch split matrix [xh|xl|xh]
__global__ __launch_bounds__(256) void k_prep(const float* __restrict__ x,
                                              const float* __restrict__ We,
                                              const float* __restrict__ Wd,
                                              const float* __restrict__ cb) {
    int bid = blockIdx.x;
    int tid = threadIdx.x;

    if (bid < 256) {   // codebook transpose
        __shared__ float t[32][33];
        int bx = bid & 15, by = bid >> 4;
        int tx = tid & 31, ty = tid >> 5;
        int xx = bx * 32 + tx;
        int y0 = by * 32;
        for (int r = ty; r < 32; r += 8)
            t[r][tx] = cb[(y0 + r) * NK + xx];
        __syncthreads();
        int xo = by * 32 + tx;
        int yo = bx * 32;
        for (int r = ty; r < 32; r += 8) {
            float v = t[tx][r];
            g_cbt[(yo + r) * ND + xo] = v;
            g_cbh[(yo + r) * ND + xo] = __float2bfloat16(v);
        }
        return;
    }
    if (bid < 578) {
        int blk = bid - 256;
        if (blk < 96) {              // wdt flip
            int e = blk * 256 + tid;
            int r = e >> 9, d = e & 511;
            int c = r >> 4, i = (r >> 2) & 3, j = r & 3;
            g_wdt[e] = Wd[(c * ND + d) * 16 + (3 - i) * 4 + (3 - j)];
        } else if (blk < 98) {       // w2
            int k = (blk - 96) * 256 + tid;
            float s = 0.f;
            for (int d = 0; d < ND; d++) {
                float v = cb[d * NK + k];
                s += v * v;
            }
            g_w2[k] = s;
        } else if (blk < 226) {      // init
            int m = (blk - 98) * 256 + tid;
            g_key[m] = 0xFFFFFFFFFFFFFFFFull;
            g_ccnt[m] = 0;
        } else {                     // We split: blk in [226,322)
            int e = (blk - 226) * 256 + tid;   // < 24576
            int d = e / 48, q = e - d * 48;
            float v = We[e];
            __nv_bfloat16 wh = __float2bfloat16(v);
            __nv_bfloat16 wl = __float2bfloat16(v - __bfloat162float(wh));
            g_wsplit[d * XP + q] = wh;
            g_wsplit[d * XP + 48 + q] = wh;
            g_wsplit[d * XP + 96 + q] = wl;
        }
        return;
    }

    // x patch split: block per (b, hl)
    int e_blk = bid - 578;         // [0, 1024)
    int b = e_blk >> 5, hl = e_blk & 31;
#pragma unroll
    for (int i = 0; i < 6; i++) {
        int e = i * 256 + tid;     // < 1536
        int row = e >> 7;          // c*4 + ii
        int col = e & 127;
        int c = row >> 2, ii = row & 3;
        float v = x[((b * NC + c) * NH + (4 * hl + ii)) * NH + col];
        int wl = col >> 2, j = col & 3;
        int q = c * 16 + ii * 4 + j;
        int base = (b * NL + hl * 32 + wl) * XP + q;
        __nv_bfloat16 xh = __float2bfloat16(v);
        __nv_bfloat16 xl = __float2bfloat16(v - __bfloat162float(xh));
        g_xsplit[base] = xh;
        g_xsplit[base + 48] = xl;
        g_xsplit[base + 96] = xh;
    }
}

// ---------------- encode GEMM: z[m][n] = xsplit[m] . wsplit[n]  (K=144, bf16 HMMA) ----------------
// Block 128m x 128n, 128 threads, warp tile 64x64 (2x2), single K pass (9 ks), 2 blocks/SM.
// Epilogue: z tile staged in reused smem (pitch 129), bias+relu, coalesced outputs.
#define EPITCH 304                     // A/B smem row pitch bytes (19 x 16B)
#define EST (128 * EPITCH)             // 38912 B per operand
#define EMM_SMEM (2 * EST)             // 77824 B

__global__ __launch_bounds__(128, 2) void k_encode_mma(const float* __restrict__ be,
                                                       float* __restrict__ out_ze) {
    extern __shared__ __align__(16) char esm2[];
    __shared__ float bsm[128];
    int tid = threadIdx.x;
    int lane = tid & 31, wrp = tid >> 5;
    int wm = wrp & 1, wn = wrp >> 1;
    int m0 = blockIdx.x * 128, n0 = blockIdx.y * 128;
    uint32_t smb = (uint32_t)__cvta_generic_to_shared(esm2);

    // fill A (xsplit rows m0..m0+127) and B (wsplit rows n0..n0+127): 19 chunks/row
#pragma unroll
    for (int i = 0; i < 19; i++) {
        int c = i * 128 + tid;         // [0, 2432)
        int r = c / 19, ch = c - r * 19;
        CP_ASYNC16(smb + r * EPITCH + ch * 16, g_xsplit + (m0 + r) * XP + ch * 8);
    }
#pragma unroll
    for (int i = 0; i < 19; i++) {
        int c = i * 128 + tid;
        int r = c / 19, ch = c - r * 19;
        CP_ASYNC16(smb + EST + r * EPITCH + ch * 16, g_wsplit + (n0 + r) * XP + ch * 8);
    }
    CP_COMMIT();
    if (tid < 128) bsm[tid] = be[n0 + tid];

    float cfr[4][8][4];
#pragma unroll
    for (int mt = 0; mt < 4; mt++)
#pragma unroll
        for (int nt = 0; nt < 8; nt++)
#pragma unroll
            for (int q = 0; q < 4; q++) cfr[mt][nt][q] = 0.f;

    CP_WAIT(0);
    __syncthreads();

#pragma unroll
    for (int ks = 0; ks < 9; ks++) {
        uint32_t afr[4][4];
#pragma unroll
        for (int mt = 0; mt < 4; mt++) {
            int r = wm * 64 + mt * 16 + ((lane >> 3) & 1) * 8 + (lane & 7);
            int cb2 = ks * 32 + (lane >> 4) * 16;
            ldsm4(afr[mt][0], afr[mt][1], afr[mt][2], afr[mt][3], smb + r * EPITCH + cb2);
        }
        uint32_t bfr[8][2];
#pragma unroll
        for (int p = 0; p < 4; p++) {
            int r = wn * 64 + p * 16 + (lane >> 4) * 8 + (lane & 7);
            int cb2 = ks * 32 + ((lane >> 3) & 1) * 16;
            uint32_t b0, b1, b2, b3;
            ldsm4(b0, b1, b2, b3, smb + EST + r * EPITCH + cb2);
            bfr[2*p][0] = b0; bfr[2*p][1] = b1; bfr[2*p+1][0] = b2; bfr[2*p+1][1] = b3;
        }
#pragma unroll
        for (int mt = 0; mt < 4; mt++)
#pragma unroll
            for (int nt = 0; nt < 8; nt++)
                mma16816(cfr[mt][nt], afr[mt], bfr[nt][0], bfr[nt][1]);
    }
    __syncthreads();   // all ldmatrix reads done; safe to reuse smem

    // stage z tile (bias + relu) into smem, pitch 129 floats
    float* zt = reinterpret_cast<float*>(esm2);
#pragma unroll
    for (int mt = 0; mt < 4; mt++)
#pragma unroll
        for (int nt = 0; nt < 8; nt++)
#pragma unroll
            for (int h = 0; h < 2; h++)
#pragma unroll
                for (int c2 = 0; c2 < 2; c2++) {
                    int lr = wm * 64 + mt * 16 + (lane >> 2) + h * 8;
                    int nl = wn * 64 + nt * 8 + (lane & 3) * 2 + c2;
                    float v = fmaxf(cfr[mt][nt][h * 2 + c2] + bsm[nl], 0.f);
                    zt[lr * 129 + nl] = v;
                }
    __syncthreads();

    // outputs
    int b = m0 >> 10;
    int hl_base = (m0 & 1023) >> 5;    // 4 consecutive hl values

    // g_zh / g_zl: rows (m0+i), cols n0+tid (lanes contiguous)
#pragma unroll 4
    for (int i = 0; i < 128; i++) {
        float v = zt[i * 129 + tid];
        __nv_bfloat16 h = __float2bfloat16(v);
        int gi = (m0 + i) * ND + n0 + tid;
        g_zh[gi] = h;
        g_zl[gi] = __float2bfloat16(v - __bfloat162float(h));
    }

    // out_ze (B,D,HL,WL): warp per (d, hl) row, lanes = wl (128B coalesced)
    for (int ro = wrp; ro < 512; ro += 4) {
        int dl = ro >> 2, hl_l = ro & 3;
        float v = zt[(hl_l * 32 + lane) * 129 + dl];
        out_ze[((b * ND + n0 + dl) * NHL + hl_base + hl_l) * NHL + lane] = v;
    }
}

// ---------------- pmat: P[k][r] = sum_d wdt[r][d] * cbt[k][d] ----------------
__global__ __launch_bounds__(256) void k_pmat() {
    int lane = threadIdx.x & 31, wrp = threadIdx.x >> 5;
    int k = blockIdx.x * 8 + wrp;
    float creg[16];
#pragma unroll
    for (int t = 0; t < 16; t++) creg[t] = g_cbt[k * ND + t * 32 + lane];
#pragma unroll 1
    for (int r = 0; r < 48; r++) {
        float s = 0.f;
        const float* wr = g_wdt + r * ND + lane;
#pragma unroll
        for (int t = 0; t < 16; t++) s += creg[t] * wr[t * 32];
#pragma unroll
        for (int off = 16; off > 0; off >>= 1) s += __shfl_xor_sync(0xffffffffu, s, off);
        if (lane == 0) g_P[k * 48 + r] = s;
    }
}

// ---------------- pass 1: bf16 HMMA GEMM + approx argmin + candidate flagging ----------------
// Measured-best config (63.0us, twice): 256 threads, 4x2 warp grid, 32x64 warp tiles,
// 2-stage cp.async double-buffer, regs=128, 2 blocks/SM (16 warps/SM for latency hiding).
#define STG_BYTES 18432
#define NN_SMEM (4 * STG_BYTES)

__device__ __forceinline__ void nn_fill(uint32_t smb, int stg, int kc, int m0, int n0, int tid) {
    uint32_t ab = smb + stg * STG_BYTES;
    uint32_t bb = smb + 2 * STG_BYTES + stg * STG_BYTES;
#pragma unroll
    for (int i = 0; i < 4; i++) {
        int u = i * 256 + tid;
        int r = u >> 3, cg = u & 7;
        CP_ASYNC16(ab + r * 144 + cg * 16, g_zh + (m0 + r) * ND + kc * 64 + cg * 8);
    }
#pragma unroll
    for (int i = 0; i < 4; i++) {
        int u = i * 256 + tid;
        int r = u >> 3, cg = u & 7;
        CP_ASYNC16(bb + r * 144 + cg * 16, g_cbh + (n0 + r) * ND + kc * 64 + cg * 8);
    }
}

__global__ __launch_bounds__(256, 2) void k_nn() {
    extern __shared__ __align__(16) char nsm[];
    __shared__ float w2s[128];
    __shared__ unsigned rmin[128];
    int tid = threadIdx.x;
    int lane = tid & 31, wrp = tid >> 5;
    int wm = wrp & 3, wn = wrp >> 2;      // 4 x 2 warp grid; warp tile 32(m) x 64(n)
    int m0 = blockIdx.x * 128, n0 = blockIdx.y * 128;
    uint32_t smb = (uint32_t)__cvta_generic_to_shared(nsm);

    if (tid < 128) { w2s[tid] = g_w2[n0 + tid]; rmin[tid] = 0xFFFFFFFFu; }

    float cfr[2][8][4];
#pragma unroll
    for (int mt = 0; mt < 2; mt++)
#pragma unroll
        for (int nt = 0; nt < 8; nt++)
#pragma unroll
            for (int q = 0; q < 4; q++) cfr[mt][nt][q] = 0.f;

    nn_fill(smb, 0, 0, m0, n0, tid);
    CP_COMMIT();

    for (int kc = 0; kc < 8; kc++) {
        if (kc < 7) { nn_fill(smb, (kc + 1) & 1, kc + 1, m0, n0, tid); CP_COMMIT(); CP_WAIT(1); }
        else        { CP_WAIT(0); }
        __syncthreads();
        uint32_t sa = smb + (kc & 1) * STG_BYTES;
        uint32_t sb = smb + 2 * STG_BYTES + (kc & 1) * STG_BYTES;
#pragma unroll
        for (int ks = 0; ks < 4; ks++) {
            uint32_t afr[2][4];
#pragma unroll
            for (int mt = 0; mt < 2; mt++) {
                int r = wm * 32 + mt * 16 + ((lane >> 3) & 1) * 8 + (lane & 7);
                int cb2 = ks * 32 + (lane >> 4) * 16;
                ldsm4(afr[mt][0], afr[mt][1], afr[mt][2], afr[mt][3], sa + r * 144 + cb2);
            }
            uint32_t bfr[8][2];
#pragma unroll
            for (int p = 0; p < 4; p++) {
                int r = wn * 64 + p * 16 + (lane >> 4) * 8 + (lane & 7);
                int cb2 = ks * 32 + ((lane >> 3) & 1) * 16;
                uint32_t b0, b1, b2, b3;
                ldsm4(b0, b1, b2, b3, sb + r * 144 + cb2);
                bfr[2*p][0] = b0; bfr[2*p][1] = b1; bfr[2*p+1][0] = b2; bfr[2*p+1][1] = b3;
            }
#pragma unroll
            for (int mt = 0; mt < 2; mt++)
#pragma unroll
                for (int nt = 0; nt < 8; nt++)
                    mma16816(cfr[mt][nt], afr[mt], bfr[nt][0], bfr[nt][1]);
        }
        __syncthreads();
    }

    // epilogue phase 1: per-row block min (smem) + global packed atomicMin
#pragma unroll
    for (int mt = 0; mt < 2; mt++) {
#pragma unroll
        for (int h = 0; h < 2; h++) {
            int lr = wm * 32 + mt * 16 + (lane >> 2) + h * 8;
            unsigned long long best = 0xFFFFFFFFFFFFFFFFull;
#pragma unroll
            for (int nt = 0; nt < 8; nt++)
#pragma unroll
                for (int c2 = 0; c2 < 2; c2++) {
                    int kl = wn * 64 + nt * 8 + (lane & 3) * 2 + c2;
                    float dist = w2s[kl] - 2.f * cfr[mt][nt][h * 2 + c2];
                    unsigned long long key =
                        ((unsigned long long)mapf(dist) << 32) | (unsigned)(n0 + kl);
                    if (key < best) best = key;
                }
            unsigned long long o1 = __shfl_xor_sync(0xffffffffu, best, 1);
            if (o1 < best) best = o1;
            unsigned long long o2 = __shfl_xor_sync(0xffffffffu, best, 2);
            if (o2 < best) best = o2;
            if ((lane & 3) == 0) {
                atomicMin(&rmin[lr], (unsigned)(best >> 32));
                atomicMin(&g_key[m0 + lr], best);
            }
        }
    }
    __syncthreads();

    // epilogue phase 2: flag candidates (store packed key) within MARGIN of block row-min
#pragma unroll
    for (int mt = 0; mt < 2; mt++) {
#pragma unroll
        for (int h = 0; h < 2; h++) {
            int lr = wm * 32 + mt * 16 + (lane >> 2) + h * 8;
            float thr = unmapf(rmin[lr]) + MARGIN;
#pragma unroll
            for (int nt = 0; nt < 8; nt++)
#pragma unroll
                for (int c2 = 0; c2 < 2; c2++) {
                    int kl = wn * 64 + nt * 8 + (lane & 3) * 2 + c2;
                    float dist = w2s[kl] - 2.f * cfr[mt][nt][h * 2 + c2];
                    if (dist <= thr) {
                        int pos = atomicAdd(&g_ccnt[m0 + lr], 1);
                        if (pos < NSLOT)
                            g_cand[(m0 + lr) * NSLOT + pos] =
                                ((unsigned long long)mapf(dist) << 32) | (unsigned)(n0 + kl);
                    }
                }
        }
    }
}

// ---------------- pass 2: exact fp32 rescore (fast path: approx winner unambiguous) ----------------
__global__ __launch_bounds__(256) void k_rescore() {
    int tid = threadIdx.x, lane = tid & 31;
    int m = blockIdx.x * 8 + (tid >> 5);

    unsigned long long gkey = g_key[m];
    float amin = unmapf((unsigned)(gkey >> 32));
    int kstar = (int)(gkey & 0xFFFFFFFFu);
    int cnt = g_ccnt[m]; if (cnt > NSLOT) cnt = NSLOT;

    unsigned long long ck = 0xFFFFFFFFFFFFFFFFull;
    if (lane < cnt) ck = g_cand[m * NSLOT + lane];
    bool qual = (lane < cnt) && (ck != gkey) &&
                (unmapf((unsigned)(ck >> 32)) <= amin + MARGIN);
    unsigned bal = __ballot_sync(0xffffffffu, qual);
    if (bal == 0) {
        if (lane == 0) g_idx[m] = kstar;
        return;
    }

    float4 z[4];
#pragma unroll
    for (int t = 0; t < 4; t++) {
        int d = t * 128 + lane * 4;
        uint2 hh = *reinterpret_cast<const uint2*>(g_zh + m * ND + d);
        uint2 ll = *reinterpret_cast<const uint2*>(g_zl + m * ND + d);
        __nv_bfloat162 h0 = *reinterpret_cast<__nv_bfloat162*>(&hh.x);
        __nv_bfloat162 h1 = *reinterpret_cast<__nv_bfloat162*>(&hh.y);
        __nv_bfloat162 l0 = *reinterpret_cast<__nv_bfloat162*>(&ll.x);
        __nv_bfloat162 l1 = *reinterpret_cast<__nv_bfloat162*>(&ll.y);
        z[t].x = __bfloat162float(h0.x) + __bfloat162float(l0.x);
        z[t].y = __bfloat162float(h0.y) + __bfloat162float(l0.y);
        z[t].z = __bfloat162float(h1.x) + __bfloat162float(l1.x);
        z[t].w = __bfloat162float(h1.y) + __bfloat162float(l1.y);
    }
    unsigned mycand = (unsigned)(ck & 0xFFFFFFFFu);
    unsigned long long best = 0xFFFFFFFFFFFFFFFFull;
    int k = kstar;
    unsigned rem = bal;
    for (;;) {
        float s = 0.f;
#pragma unroll
        for (int t = 0; t < 4; t++) {
            float4 cv = *reinterpret_cast<const float4*>(g_cbt + k * ND + t * 128 + lane * 4);
            s += z[t].x * cv.x + z[t].y * cv.y + z[t].z * cv.z + z[t].w * cv.w;
        }
#pragma unroll
        for (int off = 16; off > 0; off >>= 1) s += __shfl_xor_sync(0xffffffffu, s, off);
        float dist = g_w2[k] - 2.f * s;
        unsigned long long key = ((unsigned long long)mapf(dist) << 32) | (unsigned)k;
        if (key < best) best = key;
        if (!rem) break;
        int src = __ffs(rem) - 1;
        rem &= rem - 1;
        k = (int)__shfl_sync(0xffffffffu, mycand, src);
    }
    if (lane == 0) g_idx[m] = (int)(best & 0xFFFFFFFFu);
}

// ---------------- gather (emb) + decode-via-P (recon) ----------------
#define ZQP 517
#define GDE_SMEM (32 * ZQP * 4)   // 66176 B -> 3 blocks/SM
__global__ __launch_bounds__(512) void k_gde(const float* __restrict__ bd,
                                             float* __restrict__ out_emb,
                                             float* __restrict__ out_recon) {
    extern __shared__ float smf[];
    float* zq = smf;               // [32][ZQP]
    __shared__ int karr[32];

    int blk = blockIdx.x;
    int b = blk >> 5, hl = blk & 31;
    int tid = threadIdx.x;

    if (tid < 32) karr[tid] = g_idx[b * NL + hl * 32 + tid];
    __syncthreads();

    for (int e = tid; e < 32 * ND; e += 512) {
        int wl = e >> 9, d = e & 511;
        zq[wl * ZQP + d] = g_cbt[karr[wl] * ND + d];
    }
    __syncthreads();

    float* eb = out_emb + b * (ND * NL) + hl * 32;
    for (int e = tid; e < 16384; e += 512) {
        int d = e >> 5, wl = e & 31;
        eb[d * NL + wl] = zq[wl * ZQP + d];
    }

#pragma unroll
    for (int it = 0; it < 3; it++) {
        int o = it * 512 + tid;
        int wlo = o / 48;
        int ro = o - wlo * 48;
        float v = g_P[karr[wlo] * 48 + ro];
        int cc = ro >> 4, ii = (ro >> 2) & 3, jj = ro & 3;
        v += bd[cc];
        float s = 1.f / (1.f + __expf(-v));
        out_recon[((b * NC + cc) * NH + (4 * hl + ii)) * NH + wlo * 4 + jj] = s;
    }
}

// ---------------- launch ----------------
extern "C" void kernel_launch(void* const* d_in, const int* in_sizes, int n_in,
                              void* d_out, int out_size) {
    const float* x  = (const float*)d_in[0];
    const float* We = (const float*)d_in[1];
    const float* be = (const float*)d_in[2];
    const float* Wd = (const float*)d_in[3];
    const float* bd = (const float*)d_in[4];
    const float* cb = (const float*)d_in[5];

    float* out = (float*)d_out;
    float* out_recon = out;
    float* out_ze    = out + RECON_N;
    float* out_emb   = out + RECON_N + ZE_N;

    cudaFuncSetAttribute(k_encode_mma, cudaFuncAttributeMaxDynamicSharedMemorySize, EMM_SMEM);
    cudaFuncSetAttribute(k_nn, cudaFuncAttributeMaxDynamicSharedMemorySize, NN_SMEM);
    cudaFuncSetAttribute(k_gde, cudaFuncAttributeMaxDynamicSharedMemorySize, GDE_SMEM);

    k_prep<<<1602, 256>>>(x, We, Wd, cb);
    k_encode_mma<<<dim3(256, 4), 128, EMM_SMEM>>>(be, out_ze);
    k_pmat<<<64, 256>>>();
    k_nn<<<dim3(256, 4), 256, NN_SMEM>>>();
    k_rescore<<<4096, 256>>>();
    k_gde<<<1024, 512, GDE_SMEM>>>(bd, out_emb, out_recon);
}